// round 9
// baseline (speedup 1.0000x reference)
#include <cuda_runtime.h>
#include <cuda_fp16.h>
#include <math.h>
#include <stdint.h>

#define Bb   8
#define Nn   2048
#define FIN  256
#define FOUT 128
#define CH   64          // attn j-chunk (128-byte fp16 rows)
#define NCH  (Nn / CH)   // 32

typedef unsigned long long u64;
typedef unsigned int u32;

// Scratch (device globals: allocation-free rule)
__device__ __half g_WhT[Bb * FOUT * Nn];   // [b][f][j], fp16
__device__ __half g_Wt16[FOUT * FIN];      // [f][k], fp16 W^T
__device__ float  g_va1[FIN];              // W @ a1
__device__ float  g_va2[FIN];              // W @ a2
__device__ float  g_Ei[Bb * Nn];           // exp(f1) per i-node
__device__ float  g_Ej[Bb * Nn];           // exp(f2) per j-node
__device__ float  g_maxE2[Bb];             // per-batch max of g_Ej

// ---------------- helpers ----------------
__forceinline__ __device__ u32 pkh2(float lo, float hi) {   // lo -> low half
    u32 r; asm("cvt.rn.f16x2.f32 %0,%1,%2;" : "=r"(r) : "f"(hi), "f"(lo)); return r;
}
__forceinline__ __device__ u32 smem_u32(const void* p) {
    u32 a;
    asm("{ .reg .u64 t; cvta.to.shared.u64 t,%1; cvt.u32.u64 %0,t; }" : "=r"(a) : "l"(p));
    return a;
}
// m16n8k16 fp16 MMA, fp32 accum (legacy tensor path; compute_80+)
__forceinline__ __device__ void mma16816(float* d, const u32* a, const u32* b) {
    asm volatile(
        "mma.sync.aligned.m16n8k16.row.col.f32.f16.f16.f32 "
        "{%0,%1,%2,%3},{%4,%5,%6,%7},{%8,%9},{%0,%1,%2,%3};"
        : "+f"(d[0]), "+f"(d[1]), "+f"(d[2]), "+f"(d[3])
        : "r"(a[0]), "r"(a[1]), "r"(a[2]), "r"(a[3]), "r"(b[0]), "r"(b[1]));
}
__forceinline__ __device__ void ldmx4(u32* d, u32 addr) {
    asm volatile("ldmatrix.sync.aligned.m8n8.x4.shared.b16 {%0,%1,%2,%3},[%4];"
        : "=r"(d[0]), "=r"(d[1]), "=r"(d[2]), "=r"(d[3]) : "r"(addr));
}
#define CP_ASYNC16(sdst, gsrc) \
    asm volatile("cp.async.cg.shared.global [%0], [%1], 16;" :: "r"(sdst), "l"(gsrc))
#define CP_COMMIT()  asm volatile("cp.async.commit_group;" ::: "memory")
#define CP_WAIT0()   asm volatile("cp.async.wait_group 0;" ::: "memory")

// ============================================================
// Kernel 0: prep — va1 = W@a1, va2 = W@a2 (fp32), Wt16 = W^T fp16.
// grid 8 x 256 threads.
// ============================================================
__global__ __launch_bounds__(256) void gat_prep(
    const float* __restrict__ W, const float* __restrict__ a)
{
    const int t = threadIdx.x, bid = blockIdx.x;
    if (bid == 0) {
        float s1 = 0.f, s2 = 0.f;
        #pragma unroll 8
        for (int f = 0; f < FOUT; f++) {
            float w = W[(size_t)t * FOUT + f];
            s1 += w * a[f];
            s2 += w * a[FOUT + f];
        }
        g_va1[t] = s1; g_va2[t] = s2;
    }
    const int f  = bid * 16 + (t >> 4);
    const int k0 = (t & 15) * 16;
    __half* dst = g_Wt16 + (size_t)f * FIN + k0;
    #pragma unroll
    for (int k = 0; k < 16; k++)
        dst[k] = __float2half(W[(size_t)(k0 + k) * FOUT + f]);
}

// ============================================================
// Kernel 1: Wh = x@W via m16n8k16 fp16 MMA (fp32 accum).
// CTA: 64 i x 128 f, K=256 single shot. Fused fp32 f1/f2 (= x.va) and
// exp() epilogue; WhT fp16 written via smem transpose.
// ============================================================
#define K1_WT  0            // 128 rows x 512 B = 65536
#define K1_XH  65536        // 64 rows x 512 B  = 32768 (aliased by trans)
#define K1_VA  98304        // 2 x 256 floats   = 2048
#define K1_TOT 100352

__global__ __launch_bounds__(256, 1) void gat_gemm_wh(
    const float* __restrict__ x)
{
    extern __shared__ __align__(16) char dsm[];
    const u32 sb = smem_u32(dsm);
    float* va1_s = (float*)(dsm + K1_VA);
    float* va2_s = (float*)(dsm + K1_VA + 1024);

    const int t    = threadIdx.x;
    const int lane = t & 31;
    const int wid  = t >> 5;
    const int wr   = wid & 3;          // 16-row group (4 x 16 = 64 i)
    const int wc   = wid >> 2;         // 64-col group (2 x 64 = 128 f)
    const int g    = lane >> 2;
    const int cl   = lane & 3;
    const int sel  = lane >> 3, rin = lane & 7;
    const int b    = blockIdx.y;
    const int i0   = blockIdx.x * 64;

    // stage va
    va1_s[t] = g_va1[t];
    va2_s[t] = g_va2[t];

    // cp.async W^T fp16 [128][256] -> swizzled smem (512B rows)
    #pragma unroll
    for (int q = 0; q < 16; q++) {
        int flat = t + 256 * q;        // 0..4095 16B chunks
        int row  = flat >> 5;
        int c    = flat & 31;
        CP_ASYNC16(sb + K1_WT + row * 512 + (((u32)(c ^ (row & 7))) << 4),
                   g_Wt16 + (size_t)row * FIN + c * 8);
    }
    CP_COMMIT();
    __syncthreads();                   // va_s visible

    // x load (fp32) -> f1/f2 partials + fp16 convert -> swizzled smem
    const float* xb = x + ((size_t)b * Nn + i0) * FIN;
    const int r  = t >> 2;
    const int cg = (t & 3) * 8;
    float f1p = 0.f, f2p = 0.f;
    #pragma unroll
    for (int m = 0; m < 8; m++) {
        const int c = cg + m;
        float4 xa = *(const float4*)&xb[(size_t)r * FIN + c * 8];
        float4 xv = *(const float4*)&xb[(size_t)r * FIN + c * 8 + 4];
        float4 v1a = *(const float4*)&va1_s[c * 8];
        float4 v1b = *(const float4*)&va1_s[c * 8 + 4];
        float4 v2a = *(const float4*)&va2_s[c * 8];
        float4 v2b = *(const float4*)&va2_s[c * 8 + 4];
        f1p += xa.x*v1a.x + xa.y*v1a.y + xa.z*v1a.z + xa.w*v1a.w
             + xv.x*v1b.x + xv.y*v1b.y + xv.z*v1b.z + xv.w*v1b.w;
        f2p += xa.x*v2a.x + xa.y*v2a.y + xa.z*v2a.z + xa.w*v2a.w
             + xv.x*v2b.x + xv.y*v2b.y + xv.z*v2b.z + xv.w*v2b.w;
        uint4 hx;
        hx.x = pkh2(xa.x, xa.y); hx.y = pkh2(xa.z, xa.w);
        hx.z = pkh2(xv.x, xv.y); hx.w = pkh2(xv.z, xv.w);
        *(uint4*)(dsm + K1_XH + r * 512 + (((u32)(c ^ (r & 7))) << 4)) = hx;
    }
    f1p += __shfl_xor_sync(0xffffffffu, f1p, 1);
    f1p += __shfl_xor_sync(0xffffffffu, f1p, 2);
    f2p += __shfl_xor_sync(0xffffffffu, f2p, 1);
    f2p += __shfl_xor_sync(0xffffffffu, f2p, 2);
    if ((t & 3) == 0) {
        size_t row = (size_t)b * Nn + i0 + r;
        g_Ei[row] = __expf(f1p);
        g_Ej[row] = __expf(f2p);
    }

    CP_WAIT0();
    __syncthreads();                   // xh + Wt smem ready

    // MMA: 64x128x256
    float acc[8][4];
    #pragma unroll
    for (int nt = 0; nt < 8; nt++)
        #pragma unroll
        for (int e = 0; e < 4; e++) acc[nt][e] = 0.f;

    #pragma unroll
    for (int kb = 0; kb < 8; kb++) {   // k32 blocks
        u32 bfr[8][4];
        #pragma unroll
        for (int nt = 0; nt < 8; nt++) {
            int rr = wc * 64 + nt * 8 + rin;
            u32 c  = (u32)(kb * 4) | (u32)sel;
            ldmx4(bfr[nt], sb + K1_WT + rr * 512 + ((c ^ (u32)(rr & 7)) << 4));
        }
        #pragma unroll
        for (int h = 0; h < 2; h++) {
            int rA = wr * 16 + ((sel & 1) << 3) + rin;
            u32 cA = (u32)((kb * 2 + h) * 2) | (u32)(sel >> 1);
            u32 afr[4];
            ldmx4(afr, sb + K1_XH + rA * 512 + ((cA ^ (u32)(rA & 7)) << 4));
            #pragma unroll
            for (int nt = 0; nt < 8; nt++)
                mma16816(acc[nt], afr, &bfr[nt][h * 2]);
        }
    }

    __syncthreads();                   // all smem MMA reads done; alias trans
    __half* tr = (__half*)(dsm + K1_XH);   // [128 f][72 halves] (144B rows)

    #pragma unroll
    for (int nt = 0; nt < 8; nt++)
        #pragma unroll
        for (int h = 0; h < 2; h++)
            #pragma unroll
            for (int e = 0; e < 2; e++) {
                int f = wc * 64 + nt * 8 + cl * 2 + e;
                int j = wr * 16 + g + 8 * h;
                tr[(size_t)f * 72 + j] = __float2half(acc[nt][h * 2 + e]);
            }
    __syncthreads();

    // coalesced global write: thread -> f = t>>1, 4 x 16B chunks
    {
        const int f = t >> 1;
        const __half* trow = tr + (size_t)f * 72 + (t & 1) * 32;
        __half* dst = g_WhT + ((size_t)(b * FOUT + f)) * Nn + i0 + (t & 1) * 32;
        #pragma unroll
        for (int m = 0; m < 4; m++)
            *(uint4*)(dst + m * 8) = *(const uint4*)(trow + m * 8);
    }
}

// ============================================================
// Kernel 1b: per-batch max of g_Ej (for fp16 range scaling)
// ============================================================
__global__ __launch_bounds__(256) void gat_maxe()
{
    const int b = blockIdx.x;
    const int t = threadIdx.x;
    float m = 0.f;
    #pragma unroll
    for (int q = 0; q < 8; q++)
        m = fmaxf(m, g_Ej[(size_t)b * Nn + t + 256 * q]);
    #pragma unroll
    for (int o = 16; o > 0; o >>= 1)
        m = fmaxf(m, __shfl_xor_sync(0xffffffffu, m, o));
    __shared__ float sm[8];
    if ((t & 31) == 0) sm[t >> 5] = m;
    __syncthreads();
    if (t == 0) {
        float r = sm[0];
        #pragma unroll
        for (int w = 1; w < 8; w++) r = fmaxf(r, sm[w]);
        g_maxE2[b] = r;
    }
}

// ============================================================
// Kernel 2: fused attention, mma.sync m16n8k16 fp16 (fp32 accum).
// (unchanged from R8 passing version)
// ============================================================
#define SM_PS   0
#define SM_WS   8192
#define SM_RS   40960
#define SM_TOT  41216

__global__ __launch_bounds__(256, 3) void gat_attn(
    const int* __restrict__ adj, float* __restrict__ out)
{
    extern __shared__ __align__(16) char dsm[];
    float* rows = (float*)(dsm + SM_RS);
    const u32 sb = smem_u32(dsm);

    const int t    = threadIdx.x;
    const int lane = t & 31;
    const int wid  = t >> 5;
    const int wr   = wid & 1;
    const int wc   = wid >> 1;
    const int g    = lane >> 2;
    const int cl   = lane & 3;
    const int b    = blockIdx.y;
    const int i0   = blockIdx.x * 32;

    const int sel = lane >> 3, rin = lane & 7;
    u32 a_off[4], b_off[4][2];
    #pragma unroll
    for (int ks = 0; ks < 4; ks++) {
        int r = wr * 16 + ((sel & 1) << 3) + rin;
        int c = ks * 2 + (sel >> 1);
        a_off[ks] = (u32)(r * 128 + ((u32)(c ^ (r & 7)) << 4));
    }
    #pragma unroll
    for (int nt = 0; nt < 4; nt++)
        #pragma unroll
        for (int kb = 0; kb < 2; kb++) {
            int rr = wc * 32 + nt * 8 + rin;
            int c  = kb * 4 + sel;
            b_off[nt][kb] = (u32)(rr * 128 + ((u32)(c ^ (rr & 7)) << 4));
        }

    const int iL = t >> 3;
    const int jt8 = t & 7;
    const int jh  = jt8 * 8;
    const u32 pst = (u32)(iL * 128 + (((u32)(jt8 ^ (iL & 7))) << 4));

    const float c1  = g_Ei[(size_t)b * Nn + i0 + iL];
    const float mE2 = g_maxE2[b];
    const float thrE = 1.0f / c1;
    float pm = c1 * mE2;
    pm = (pm >= 1.f) ? pm : pm * pm;
    int ex = (int)((__float_as_uint(pm) >> 23) & 255u) - 127;
    int kk = ex - 11; if (kk < 0) kk = 0;
    const float scale = __uint_as_float((u32)(127 - kk) << 23);
    const float c1s = c1 * scale;
    const float c2s = c1 * c1 * scale;

    const int*   arow = adj  + ((size_t)(b * Nn + i0 + iL)) * Nn + jh;
    const float* Ejb  = g_Ej + (size_t)b * Nn + jh;
    const __half* whtb = g_WhT + (size_t)b * FOUT * Nn;

    float acc[4][4];
    #pragma unroll
    for (int nt = 0; nt < 4; nt++)
        #pragma unroll
        for (int e = 0; e < 4; e++) acc[nt][e] = 0.f;

    int4   sav[2];
    float4 sev[2];
    float  rs = 0.f;

    #define ISSUE_G(c_) do {                                              \
        const int _j0 = (c_) * CH;                                        \
        sav[0] = *(const int4*)&arow[_j0];                                \
        sav[1] = *(const int4*)&arow[_j0 + 4];                            \
        sev[0] = *(const float4*)&Ejb[_j0];                               \
        sev[1] = *(const float4*)&Ejb[_j0 + 4];                           \
    } while (0)

    #define ISSUE_W(c_, buf_) do {                                        \
        const int _j0 = (c_) * CH;                                        \
        const u32 _wb = sb + SM_WS + (buf_) * 16384;                      \
        _Pragma("unroll")                                                 \
        for (int q = 0; q < 4; q++) {                                     \
            int flat = t + 256 * q;                                       \
            int row  = flat >> 3;                                         \
            int jc   = flat & 7;                                          \
            u32 sidx = (u32)(row * 128 + (((u32)(jc ^ (row & 7))) << 4)); \
            CP_ASYNC16(_wb + sidx,                                        \
                       &whtb[(size_t)row * Nn + _j0 + jc * 8]);           \
        }                                                                  \
        CP_COMMIT();                                                       \
    } while (0)

    #define FINISH(buf_) do {                                              \
        const int*   _a = (const int*)sav;                                 \
        const float* _e = (const float*)sev;                               \
        uint4 pv; u32* pw = (u32*)&pv;                                     \
        _Pragma("unroll")                                                  \
        for (int u = 0; u < 4; u++) {                                      \
            float E0 = _e[u * 2], E1 = _e[u * 2 + 1];                      \
            float m0 = (E0 >= thrE) ? c1s : c2s * E0;                      \
            float m1 = (E1 >= thrE) ? c1s : c2s * E1;                      \
            float p0 = (_a[u * 2]     > 0) ? m0 * E0 : 0.f;                \
            float p1 = (_a[u * 2 + 1] > 0) ? m1 * E1 : 0.f;                \
            u32 h2 = pkh2(p0, p1);                                         \
            pw[u] = h2;                                                    \
            rs += __half2float(((const __half2*)&h2)->x)                   \
                + __half2float(((const __half2*)&h2)->y);                  \
        }                                                                   \
        *(uint4*)(dsm + SM_PS + (buf_) * 4096 + pst) = pv;                 \
    } while (0)

    ISSUE_W(0, 0);
    ISSUE_G(0);
    FINISH(0);
    CP_WAIT0();
    __syncthreads();

    for (int c = 0; c < NCH; c++) {
        const int s = c & 1;
        if (c < NCH - 1) { ISSUE_G(c + 1); ISSUE_W(c + 1, s ^ 1); }

        {
            const u32 pb = sb + SM_PS + s * 4096;
            const u32 wb = sb + SM_WS + s * 16384;
            #pragma unroll
            for (int kb = 0; kb < 2; kb++) {
                u32 bfr[4][4];
                #pragma unroll
                for (int nt = 0; nt < 4; nt++)
                    ldmx4(bfr[nt], wb + b_off[nt][kb]);
                #pragma unroll
                for (int h = 0; h < 2; h++) {
                    u32 afr[4];
                    ldmx4(afr, pb + a_off[kb * 2 + h]);
                    #pragma unroll
                    for (int nt = 0; nt < 4; nt++)
                        mma16816(acc[nt], afr, &bfr[nt][h * 2]);
                }
            }
        }

        if (c < NCH - 1) FINISH(s ^ 1);
        CP_WAIT0();
        __syncthreads();
    }

    rs += __shfl_xor_sync(0xffffffffu, rs, 1);
    rs += __shfl_xor_sync(0xffffffffu, rs, 2);
    rs += __shfl_xor_sync(0xffffffffu, rs, 4);
    if ((t & 7) == 0) rows[iL] = rs;
    __syncthreads();

    #pragma unroll
    for (int h = 0; h < 2; h++) {
        const int row = wr * 16 + g + h * 8;
        const float inv = 1.0f / rows[row];
        float* orow = out + ((size_t)(b * Nn + i0 + row)) * FOUT + wc * 32 + cl * 2;
        #pragma unroll
        for (int nt = 0; nt < 4; nt++) {
            float h0 = acc[nt][h * 2 + 0] * inv;
            float h1 = acc[nt][h * 2 + 1] * inv;
            h0 = (h0 > 0.f) ? h0 : expm1f(h0);
            h1 = (h1 > 0.f) ? h1 : expm1f(h1);
            float2 o = make_float2(h0, h1);
            *(float2*)&orow[nt * 8] = o;
        }
    }
}

// ============================================================
extern "C" void kernel_launch(void* const* d_in, const int* in_sizes, int n_in,
                              void* d_out, int out_size)
{
    const float* x   = (const float*)d_in[0];   // [8,2048,256] f32
    const int*   adj = (const int*)  d_in[1];   // [8,2048,2048] i32
    const float* W   = (const float*)d_in[2];   // [256,128] f32
    const float* a   = (const float*)d_in[3];   // [256,1] f32
    float*       out = (float*)d_out;           // [8,2048,128] f32

    gat_prep<<<8, 256>>>(W, a);

    cudaFuncSetAttribute(gat_gemm_wh, cudaFuncAttributeMaxDynamicSharedMemorySize, K1_TOT);
    dim3 g1(Nn / 64, Bb);
    gat_gemm_wh<<<g1, 256, K1_TOT>>>(x);

    gat_maxe<<<Bb, 256>>>();

    dim3 g2(Nn / 32, Bb);
    gat_attn<<<g2, 256, SM_TOT>>>(adj, out);
}

// round 11
// speedup vs baseline: 1.1365x; 1.1365x over previous
#include <cuda_runtime.h>
#include <cuda_fp16.h>
#include <math.h>
#include <stdint.h>

#define Bb   8
#define Nn   2048
#define FIN  256
#define FOUT 128
#define CH   64          // attn j-chunk (128-byte fp16 rows)
#define NCH  (Nn / CH)   // 32

typedef unsigned long long u64;
typedef unsigned int u32;

// Scratch (device globals: allocation-free rule)
__device__ __half g_WhT[Bb * FOUT * Nn];   // [b][f][j], fp16
__device__ __half g_Wt16[FOUT * FIN];      // [f][k], fp16 W^T
__device__ float  g_va1[FIN];              // W @ a1
__device__ float  g_va2[FIN];              // W @ a2
__device__ float  g_Ei[Bb * Nn];           // exp(f1) per i-node
__device__ float  g_Ej[Bb * Nn];           // exp(f2) per j-node
__device__ float  g_maxE2[Bb];             // per-batch max of g_Ej

// ---------------- helpers ----------------
__forceinline__ __device__ u32 pkh2(float lo, float hi) {   // lo -> low half
    u32 r; asm("cvt.rn.f16x2.f32 %0,%1,%2;" : "=r"(r) : "f"(hi), "f"(lo)); return r;
}
__forceinline__ __device__ u32 smem_u32(const void* p) {
    u32 a;
    asm("{ .reg .u64 t; cvta.to.shared.u64 t,%1; cvt.u32.u64 %0,t; }" : "=r"(a) : "l"(p));
    return a;
}
__forceinline__ __device__ void mma16816(float* d, const u32* a, const u32* b) {
    asm volatile(
        "mma.sync.aligned.m16n8k16.row.col.f32.f16.f16.f32 "
        "{%0,%1,%2,%3},{%4,%5,%6,%7},{%8,%9},{%0,%1,%2,%3};"
        : "+f"(d[0]), "+f"(d[1]), "+f"(d[2]), "+f"(d[3])
        : "r"(a[0]), "r"(a[1]), "r"(a[2]), "r"(a[3]), "r"(b[0]), "r"(b[1]));
}
__forceinline__ __device__ void ldmx4(u32* d, u32 addr) {
    asm volatile("ldmatrix.sync.aligned.m8n8.x4.shared.b16 {%0,%1,%2,%3},[%4];"
        : "=r"(d[0]), "=r"(d[1]), "=r"(d[2]), "=r"(d[3]) : "r"(addr));
}
#define CP_ASYNC16(sdst, gsrc) \
    asm volatile("cp.async.cg.shared.global [%0], [%1], 16;" :: "r"(sdst), "l"(gsrc))
#define CP_COMMIT()  asm volatile("cp.async.commit_group;" ::: "memory")
#define CP_WAIT0()   asm volatile("cp.async.wait_group 0;" ::: "memory")

// ============================================================
// Kernel 0: prep — va1 = W@a1, va2 = W@a2 (fp32), Wt16 = W^T fp16.
// ============================================================
__global__ __launch_bounds__(256) void gat_prep(
    const float* __restrict__ W, const float* __restrict__ a)
{
    const int t = threadIdx.x, bid = blockIdx.x;
    if (bid == 0) {
        float s1 = 0.f, s2 = 0.f;
        #pragma unroll 8
        for (int f = 0; f < FOUT; f++) {
            float w = W[(size_t)t * FOUT + f];
            s1 += w * a[f];
            s2 += w * a[FOUT + f];
        }
        g_va1[t] = s1; g_va2[t] = s2;
    }
    const int f  = bid * 16 + (t >> 4);
    const int k0 = (t & 15) * 16;
    __half* dst = g_Wt16 + (size_t)f * FIN + k0;
    #pragma unroll
    for (int k = 0; k < 16; k++)
        dst[k] = __float2half(W[(size_t)(k0 + k) * FOUT + f]);
}

// ============================================================
// Kernel 1: Wh = x@W via fp16 MMA, CTA = 64 i x 64 f (f-half by
// blockIdx.z), occ 2. Fused fp32 f1/f2 + exp epilogue; WhT fp16 out.
// ============================================================
#define K1_WT  0            // 64 f rows x 512 B = 32768
#define K1_XH  32768        // 64 i rows x 512 B = 32768 (aliased by trans)
#define K1_VA  65536        // 2 x 256 floats = 2048
#define K1_TOT 67584

__global__ __launch_bounds__(256, 2) void gat_gemm_wh(
    const float* __restrict__ x)
{
    extern __shared__ __align__(16) char dsm[];
    const u32 sb = smem_u32(dsm);
    float* va1_s = (float*)(dsm + K1_VA);
    float* va2_s = (float*)(dsm + K1_VA + 1024);

    const int t    = threadIdx.x;
    const int lane = t & 31;
    const int wid  = t >> 5;
    const int wr   = wid & 3;          // 4 x 16 = 64 i rows
    const int wc   = wid >> 2;         // 2 x 32 = 64 f cols
    const int g    = lane >> 2;
    const int cl   = lane & 3;
    const int sel  = lane >> 3, rin = lane & 7;
    const int b    = blockIdx.y;
    const int fh   = blockIdx.z;       // f half (0/1)
    const int i0   = blockIdx.x * 64;

    va1_s[t] = g_va1[t];
    va2_s[t] = g_va2[t];

    // cp.async W^T half [64 f][256 k] fp16 -> swizzled smem (512B rows)
    #pragma unroll
    for (int q = 0; q < 8; q++) {
        int flat = t + 256 * q;        // 0..2047 16B chunks
        int row  = flat >> 5;
        int c    = flat & 31;
        CP_ASYNC16(sb + K1_WT + row * 512 + (((u32)(c ^ (row & 7))) << 4),
                   g_Wt16 + (size_t)(fh * 64 + row) * FIN + c * 8);
    }
    CP_COMMIT();
    __syncthreads();                   // va_s visible

    // x load (fp32) -> f1/f2 partials + fp16 convert -> swizzled smem
    const float* xb = x + ((size_t)b * Nn + i0) * FIN;
    const int r  = t >> 2;
    const int cg = (t & 3) * 8;
    float f1p = 0.f, f2p = 0.f;
    #pragma unroll
    for (int m = 0; m < 8; m++) {
        const int c = cg + m;
        float4 xa = *(const float4*)&xb[(size_t)r * FIN + c * 8];
        float4 xv = *(const float4*)&xb[(size_t)r * FIN + c * 8 + 4];
        float4 v1a = *(const float4*)&va1_s[c * 8];
        float4 v1b = *(const float4*)&va1_s[c * 8 + 4];
        float4 v2a = *(const float4*)&va2_s[c * 8];
        float4 v2b = *(const float4*)&va2_s[c * 8 + 4];
        f1p += xa.x*v1a.x + xa.y*v1a.y + xa.z*v1a.z + xa.w*v1a.w
             + xv.x*v1b.x + xv.y*v1b.y + xv.z*v1b.z + xv.w*v1b.w;
        f2p += xa.x*v2a.x + xa.y*v2a.y + xa.z*v2a.z + xa.w*v2a.w
             + xv.x*v2b.x + xv.y*v2b.y + xv.z*v2b.z + xv.w*v2b.w;
        uint4 hx;
        hx.x = pkh2(xa.x, xa.y); hx.y = pkh2(xa.z, xa.w);
        hx.z = pkh2(xv.x, xv.y); hx.w = pkh2(xv.z, xv.w);
        *(uint4*)(dsm + K1_XH + r * 512 + (((u32)(c ^ (r & 7))) << 4)) = hx;
    }
    f1p += __shfl_xor_sync(0xffffffffu, f1p, 1);
    f1p += __shfl_xor_sync(0xffffffffu, f1p, 2);
    f2p += __shfl_xor_sync(0xffffffffu, f2p, 1);
    f2p += __shfl_xor_sync(0xffffffffu, f2p, 2);
    if ((t & 3) == 0) {                 // both f-halves write identical values
        size_t row = (size_t)b * Nn + i0 + r;
        g_Ei[row] = __expf(f1p);
        g_Ej[row] = __expf(f2p);
    }

    CP_WAIT0();
    __syncthreads();                   // xh + Wt smem ready

    // MMA: 64 x 64 x 256
    float acc[4][4];
    #pragma unroll
    for (int nt = 0; nt < 4; nt++)
        #pragma unroll
        for (int e = 0; e < 4; e++) acc[nt][e] = 0.f;

    #pragma unroll
    for (int kb = 0; kb < 8; kb++) {   // k32 blocks
        u32 bfr[4][4];
        #pragma unroll
        for (int nt = 0; nt < 4; nt++) {
            int rr = wc * 32 + nt * 8 + rin;
            u32 c  = (u32)(kb * 4) | (u32)sel;
            ldmx4(bfr[nt], sb + K1_WT + rr * 512 + ((c ^ (u32)(rr & 7)) << 4));
        }
        #pragma unroll
        for (int h = 0; h < 2; h++) {
            int rA = wr * 16 + ((sel & 1) << 3) + rin;
            u32 cA = (u32)((kb * 2 + h) * 2) | (u32)(sel >> 1);
            u32 afr[4];
            ldmx4(afr, sb + K1_XH + rA * 512 + ((cA ^ (u32)(rA & 7)) << 4));
            #pragma unroll
            for (int nt = 0; nt < 4; nt++)
                mma16816(acc[nt], afr, &bfr[nt][h * 2]);
        }
    }

    __syncthreads();                   // MMA smem reads done; alias trans
    __half* tr = (__half*)(dsm + K1_XH);   // [64 f][72 halves]

    #pragma unroll
    for (int nt = 0; nt < 4; nt++)
        #pragma unroll
        for (int h = 0; h < 2; h++)
            #pragma unroll
            for (int e = 0; e < 2; e++) {
                int f = wc * 32 + nt * 8 + cl * 2 + e;
                int j = wr * 16 + g + 8 * h;
                tr[(size_t)f * 72 + j] = __float2half(acc[nt][h * 2 + e]);
            }
    __syncthreads();

    // coalesced global write: thread -> local f = t>>2, 2 x 16B chunks
    {
        const int f   = t >> 2;
        const int seg = (t & 3) * 16;
        const __half* trow = tr + (size_t)f * 72 + seg;
        __half* dst = g_WhT + ((size_t)(b * FOUT + fh * 64 + f)) * Nn + i0 + seg;
        *(uint4*)(dst)     = *(const uint4*)(trow);
        *(uint4*)(dst + 8) = *(const uint4*)(trow + 8);
    }
}

// ============================================================
// Kernel 1b: per-batch max of g_Ej (for fp16 range scaling)
// ============================================================
__global__ __launch_bounds__(256) void gat_maxe()
{
    const int b = blockIdx.x;
    const int t = threadIdx.x;
    float m = 0.f;
    #pragma unroll
    for (int q = 0; q < 8; q++)
        m = fmaxf(m, g_Ej[(size_t)b * Nn + t + 256 * q]);
    #pragma unroll
    for (int o = 16; o > 0; o >>= 1)
        m = fmaxf(m, __shfl_xor_sync(0xffffffffu, m, o));
    __shared__ float sm[8];
    if ((t & 31) == 0) sm[t >> 5] = m;
    __syncthreads();
    if (t == 0) {
        float r = sm[0];
        #pragma unroll
        for (int w = 1; w < 8; w++) r = fmaxf(r, sm[w]);
        g_maxE2[b] = r;
    }
}

// ============================================================
// Kernel 2: fused attention, mma.sync m16n8k16 fp16 (fp32 accum).
// CTA: 64 i x 128 f (grid 256, occ 2). 8 warps: wr=wid&1 (32 i),
// wc=wid>>1 (32 f), mt=2. j chunks of 64, double-buffered.
// ============================================================
#define SM_PS   0                        // 2 * 64*128B  = 16384
#define SM_WS   16384                    // 2 * 128*128B = 32768
#define SM_RS   49152                    // 64 floats
#define SM_TOT  49408

__global__ __launch_bounds__(256, 2) void gat_attn(
    const int* __restrict__ adj, float* __restrict__ out)
{
    extern __shared__ __align__(16) char dsm[];
    float* rows = (float*)(dsm + SM_RS);
    const u32 sb = smem_u32(dsm);

    const int t    = threadIdx.x;
    const int lane = t & 31;
    const int wid  = t >> 5;
    const int wr   = wid & 1;           // 32-row half of 64
    const int wc   = wid >> 1;          // 32-col group of 128
    const int g    = lane >> 2;
    const int cl   = lane & 3;
    const int b    = blockIdx.y;
    const int i0   = blockIdx.x * 64;

    const int sel = lane >> 3, rin = lane & 7;
    u32 a_off[2][4], b_off[4][2];
    #pragma unroll
    for (int mt = 0; mt < 2; mt++)
        #pragma unroll
        for (int ks = 0; ks < 4; ks++) {
            int r = wr * 32 + mt * 16 + ((sel & 1) << 3) + rin;
            int c = ks * 2 + (sel >> 1);
            a_off[mt][ks] = (u32)(r * 128 + ((u32)(c ^ (r & 7)) << 4));
        }
    #pragma unroll
    for (int nt = 0; nt < 4; nt++)
        #pragma unroll
        for (int kb = 0; kb < 2; kb++) {
            int rr = wc * 32 + nt * 8 + rin;
            int c  = kb * 4 + sel;
            b_off[nt][kb] = (u32)(rr * 128 + ((u32)(c ^ (rr & 7)) << 4));
        }

    // builder mapping: row iL = t>>2 (64 rows), 16 j's at jh
    const int iL = t >> 2;
    const int jq = t & 3;
    const int jh = jq * 16;
    u32 pst[2];
    #pragma unroll
    for (int q = 0; q < 2; q++)
        pst[q] = (u32)(iL * 128 + (((u32)((jq * 2 + q) ^ (iL & 7))) << 4));

    const float c1  = g_Ei[(size_t)b * Nn + i0 + iL];
    const float mE2 = g_maxE2[b];
    const float thrE = 1.0f / c1;
    float pm = c1 * mE2;
    pm = (pm >= 1.f) ? pm : pm * pm;
    int ex = (int)((__float_as_uint(pm) >> 23) & 255u) - 127;
    int kk = ex - 11; if (kk < 0) kk = 0;
    const float scale = __uint_as_float((u32)(127 - kk) << 23);
    const float c1s = c1 * scale;
    const float c2s = c1 * c1 * scale;

    const int*   arow = adj  + ((size_t)(b * Nn + i0 + iL)) * Nn + jh;
    const float* Ejb  = g_Ej + (size_t)b * Nn + jh;
    const __half* whtb = g_WhT + (size_t)b * FOUT * Nn;

    float acc[2][4][4];
    #pragma unroll
    for (int mt = 0; mt < 2; mt++)
        #pragma unroll
        for (int nt = 0; nt < 4; nt++)
            #pragma unroll
            for (int e = 0; e < 4; e++) acc[mt][nt][e] = 0.f;

    int4   sav[4];
    float4 sev[4];
    float  rs = 0.f;

    #define ISSUE_G(c_) do {                                              \
        const int _j0 = (c_) * CH;                                        \
        _Pragma("unroll")                                                 \
        for (int q = 0; q < 4; q++) {                                     \
            sav[q] = *(const int4*)&arow[_j0 + q * 4];                    \
            sev[q] = *(const float4*)&Ejb[_j0 + q * 4];                   \
        }                                                                  \
    } while (0)

    #define ISSUE_W(c_, buf_) do {                                        \
        const int _j0 = (c_) * CH;                                        \
        const u32 _wb = sb + SM_WS + (buf_) * 16384;                      \
        _Pragma("unroll")                                                 \
        for (int q = 0; q < 4; q++) {                                     \
            int flat = t + 256 * q;                                       \
            int row  = flat >> 3;                                         \
            int jc   = flat & 7;                                          \
            u32 sidx = (u32)(row * 128 + (((u32)(jc ^ (row & 7))) << 4)); \
            CP_ASYNC16(_wb + sidx,                                        \
                       &whtb[(size_t)row * Nn + _j0 + jc * 8]);           \
        }                                                                  \
        CP_COMMIT();                                                       \
    } while (0)

    #define FINISH(buf_) do {                                              \
        const int*   _a = (const int*)sav;                                 \
        const float* _e = (const float*)sev;                               \
        _Pragma("unroll")                                                   \
        for (int q = 0; q < 2; q++) {                                       \
            uint4 pv; u32* pw = (u32*)&pv;                                  \
            _Pragma("unroll")                                               \
            for (int u = 0; u < 4; u++) {                                   \
                int i2 = q * 8 + u * 2;                                     \
                float E0 = _e[i2], E1 = _e[i2 + 1];                         \
                float m0 = (E0 >= thrE) ? c1s : c2s * E0;                   \
                float m1 = (E1 >= thrE) ? c1s : c2s * E1;                   \
                float p0 = (_a[i2]     > 0) ? m0 * E0 : 0.f;                \
                float p1 = (_a[i2 + 1] > 0) ? m1 * E1 : 0.f;                \
                u32 h2 = pkh2(p0, p1);                                      \
                pw[u] = h2;                                                 \
                rs += __half2float(((const __half2*)&h2)->x)                \
                    + __half2float(((const __half2*)&h2)->y);               \
            }                                                                \
            *(uint4*)(dsm + SM_PS + (buf_) * 8192 + pst[q]) = pv;           \
        }                                                                    \
    } while (0)

    ISSUE_W(0, 0);
    ISSUE_G(0);
    FINISH(0);
    CP_WAIT0();
    __syncthreads();

    for (int c = 0; c < NCH; c++) {
        const int s = c & 1;
        if (c < NCH - 1) { ISSUE_G(c + 1); ISSUE_W(c + 1, s ^ 1); }

        {
            const u32 pb = sb + SM_PS + s * 8192;
            const u32 wb = sb + SM_WS + s * 16384;
            #pragma unroll
            for (int kb = 0; kb < 2; kb++) {
                u32 bfr[4][4];
                #pragma unroll
                for (int nt = 0; nt < 4; nt++)
                    ldmx4(bfr[nt], wb + b_off[nt][kb]);
                #pragma unroll
                for (int h = 0; h < 2; h++) {
                    u32 afr[2][4];
                    ldmx4(afr[0], pb + a_off[0][kb * 2 + h]);
                    ldmx4(afr[1], pb + a_off[1][kb * 2 + h]);
                    #pragma unroll
                    for (int nt = 0; nt < 4; nt++) {
                        mma16816(acc[0][nt], afr[0], &bfr[nt][h * 2]);
                        mma16816(acc[1][nt], afr[1], &bfr[nt][h * 2]);
                    }
                }
            }
        }

        if (c < NCH - 1) FINISH(s ^ 1);
        CP_WAIT0();
        __syncthreads();
    }

    // rowsum: threads t..t|3 share builder row iL
    rs += __shfl_xor_sync(0xffffffffu, rs, 1);
    rs += __shfl_xor_sync(0xffffffffu, rs, 2);
    if ((t & 3) == 0) rows[iL] = rs;
    __syncthreads();

    // epilogue
    #pragma unroll
    for (int mt = 0; mt < 2; mt++)
        #pragma unroll
        for (int h = 0; h < 2; h++) {
            const int row = wr * 32 + mt * 16 + g + h * 8;
            const float inv = 1.0f / rows[row];
            float* orow = out + ((size_t)(b * Nn + i0 + row)) * FOUT + wc * 32 + cl * 2;
            #pragma unroll
            for (int nt = 0; nt < 4; nt++) {
                float h0 = acc[mt][nt][h * 2 + 0] * inv;
                float h1 = acc[mt][nt][h * 2 + 1] * inv;
                h0 = (h0 > 0.f) ? h0 : expm1f(h0);
                h1 = (h1 > 0.f) ? h1 : expm1f(h1);
                float2 o = make_float2(h0, h1);
                *(float2*)&orow[nt * 8] = o;
            }
        }
}

// ============================================================
extern "C" void kernel_launch(void* const* d_in, const int* in_sizes, int n_in,
                              void* d_out, int out_size)
{
    const float* x   = (const float*)d_in[0];   // [8,2048,256] f32
    const int*   adj = (const int*)  d_in[1];   // [8,2048,2048] i32
    const float* W   = (const float*)d_in[2];   // [256,128] f32
    const float* a   = (const float*)d_in[3];   // [256,1] f32
    float*       out = (float*)d_out;           // [8,2048,128] f32

    gat_prep<<<8, 256>>>(W, a);

    cudaFuncSetAttribute(gat_gemm_wh, cudaFuncAttributeMaxDynamicSharedMemorySize, K1_TOT);
    cudaFuncSetAttribute(gat_attn,    cudaFuncAttributeMaxDynamicSharedMemorySize, SM_TOT);

    dim3 g1(Nn / 64, Bb, 2);
    gat_gemm_wh<<<g1, 256, K1_TOT>>>(x);

    gat_maxe<<<Bb, 256>>>();

    dim3 g2(Nn / 64, Bb);
    gat_attn<<<g2, 256, SM_TOT>>>(adj, out);
}

// round 12
// speedup vs baseline: 1.1815x; 1.0396x over previous
#include <cuda_runtime.h>
#include <cuda_fp16.h>
#include <math.h>
#include <stdint.h>

#define Bb   8
#define Nn   2048
#define FIN  256
#define FOUT 128
#define CH   64          // attn j-chunk (128-byte fp16 rows)
#define NCH  (Nn / CH)   // 32

typedef unsigned long long u64;
typedef unsigned int u32;

// Scratch (device globals: allocation-free rule)
__device__ __half g_WhT[Bb * FOUT * Nn];   // [b][f][j], fp16
__device__ __half g_xh[Bb * Nn * FIN];     // [b][i][k], fp16 x
__device__ __half g_Wt16[FOUT * FIN];      // [f][k], fp16 W^T
__device__ float  g_va1[FIN];              // W @ a1
__device__ float  g_va2[FIN];              // W @ a2
__device__ float  g_Ei[Bb * Nn];           // exp(f1) per i-node
__device__ float  g_Ej[Bb * Nn];           // exp(f2) per j-node
__device__ float  g_maxE2[Bb];             // per-batch max of g_Ej

// ---------------- helpers ----------------
__forceinline__ __device__ u32 pkh2(float lo, float hi) {   // lo -> low half
    u32 r; asm("cvt.rn.f16x2.f32 %0,%1,%2;" : "=r"(r) : "f"(hi), "f"(lo)); return r;
}
__forceinline__ __device__ u32 smem_u32(const void* p) {
    u32 a;
    asm("{ .reg .u64 t; cvta.to.shared.u64 t,%1; cvt.u32.u64 %0,t; }" : "=r"(a) : "l"(p));
    return a;
}
__forceinline__ __device__ void mma16816(float* d, const u32* a, const u32* b) {
    asm volatile(
        "mma.sync.aligned.m16n8k16.row.col.f32.f16.f16.f32 "
        "{%0,%1,%2,%3},{%4,%5,%6,%7},{%8,%9},{%0,%1,%2,%3};"
        : "+f"(d[0]), "+f"(d[1]), "+f"(d[2]), "+f"(d[3])
        : "r"(a[0]), "r"(a[1]), "r"(a[2]), "r"(a[3]), "r"(b[0]), "r"(b[1]));
}
__forceinline__ __device__ void ldmx4(u32* d, u32 addr) {
    asm volatile("ldmatrix.sync.aligned.m8n8.x4.shared.b16 {%0,%1,%2,%3},[%4];"
        : "=r"(d[0]), "=r"(d[1]), "=r"(d[2]), "=r"(d[3]) : "r"(addr));
}
#define CP_ASYNC16(sdst, gsrc) \
    asm volatile("cp.async.cg.shared.global [%0], [%1], 16;" :: "r"(sdst), "l"(gsrc))
#define CP_COMMIT()  asm volatile("cp.async.commit_group;" ::: "memory")
#define CP_WAIT0()   asm volatile("cp.async.wait_group 0;" ::: "memory")

// ============================================================
// Kernel 0: prep — va1 = W@a1, va2 = W@a2 (fp32), Wt16 = W^T fp16.
// ============================================================
__global__ __launch_bounds__(256) void gat_prep(
    const float* __restrict__ W, const float* __restrict__ a)
{
    const int t = threadIdx.x, bid = blockIdx.x;
    if (bid == 0) {
        float s1 = 0.f, s2 = 0.f;
        #pragma unroll 8
        for (int f = 0; f < FOUT; f++) {
            float w = W[(size_t)t * FOUT + f];
            s1 += w * a[f];
            s2 += w * a[FOUT + f];
        }
        g_va1[t] = s1; g_va2[t] = s2;
    }
    const int f  = bid * 16 + (t >> 4);
    const int k0 = (t & 15) * 16;
    __half* dst = g_Wt16 + (size_t)f * FIN + k0;
    #pragma unroll
    for (int k = 0; k < 16; k++)
        dst[k] = __float2half(W[(size_t)(k0 + k) * FOUT + f]);
}

// ============================================================
// Kernel 0b: xcvt — x fp32 -> fp16 g_xh; fused fp32 f1/f2 + exp.
// Block: 64 rows, 4 threads/row (64 contiguous k each). Grid 256.
// ============================================================
__global__ __launch_bounds__(256) void gat_xcvt(const float* __restrict__ x)
{
    __shared__ float va1s[FIN], va2s[FIN];
    const int t = threadIdx.x;
    va1s[t] = g_va1[t];
    va2s[t] = g_va2[t];
    __syncthreads();

    const int R  = blockIdx.x * 64 + (t >> 2);   // global row (b*Nn+i)
    const int k0 = (t & 3) * 64;
    const float* xr = x + (size_t)R * FIN + k0;

    u32 hbuf[32];
    float f1p = 0.f, f2p = 0.f;
    #pragma unroll
    for (int m = 0; m < 16; m++) {
        float4 xv = *(const float4*)&xr[m * 4];
        float4 v1 = *(const float4*)&va1s[k0 + m * 4];
        float4 v2 = *(const float4*)&va2s[k0 + m * 4];
        f1p += xv.x*v1.x + xv.y*v1.y + xv.z*v1.z + xv.w*v1.w;
        f2p += xv.x*v2.x + xv.y*v2.y + xv.z*v2.z + xv.w*v2.w;
        hbuf[m * 2 + 0] = pkh2(xv.x, xv.y);
        hbuf[m * 2 + 1] = pkh2(xv.z, xv.w);
    }
    __half* xd = g_xh + (size_t)R * FIN + k0;
    #pragma unroll
    for (int q = 0; q < 8; q++)
        *(uint4*)(xd + q * 8) = *(uint4*)&hbuf[q * 4];

    f1p += __shfl_xor_sync(0xffffffffu, f1p, 1);
    f1p += __shfl_xor_sync(0xffffffffu, f1p, 2);
    f2p += __shfl_xor_sync(0xffffffffu, f2p, 1);
    f2p += __shfl_xor_sync(0xffffffffu, f2p, 2);
    if ((t & 3) == 0) {
        g_Ei[R] = __expf(f1p);
        g_Ej[R] = __expf(f2p);
    }
}

// ============================================================
// Kernel 1: Wh = x@W — pure fp16 GEMM (attn geometry reused).
// CTA: 64 i x 128 f, K chunks of 64, double-buffered cp.async A+B.
// Epilogue: smem transpose -> WhT[b][f][j] fp16.
// ============================================================
#define K1_A   0            // 2 x 64 rows x 128 B  = 16384
#define K1_B   16384        // 2 x 128 rows x 128 B = 32768
#define K1_TOT 49152

__global__ __launch_bounds__(256, 2) void gat_gemm_wh()
{
    extern __shared__ __align__(16) char dsm[];
    const u32 sb = smem_u32(dsm);

    const int t    = threadIdx.x;
    const int lane = t & 31;
    const int wid  = t >> 5;
    const int wr   = wid & 1;           // 32-row half of 64 i
    const int wc   = wid >> 1;          // 32-col group of 128 f
    const int g    = lane >> 2;
    const int cl   = lane & 3;
    const int sel  = lane >> 3, rin = lane & 7;
    const int b    = blockIdx.y;
    const int i0   = blockIdx.x * 64;

    // fragment offsets (identical scheme to attn)
    u32 a_off[2][4], b_off[4][2];
    #pragma unroll
    for (int mt = 0; mt < 2; mt++)
        #pragma unroll
        for (int ks = 0; ks < 4; ks++) {
            int r = wr * 32 + mt * 16 + ((sel & 1) << 3) + rin;
            int c = ks * 2 + (sel >> 1);
            a_off[mt][ks] = (u32)(r * 128 + ((u32)(c ^ (r & 7)) << 4));
        }
    #pragma unroll
    for (int nt = 0; nt < 4; nt++)
        #pragma unroll
        for (int kb = 0; kb < 2; kb++) {
            int rr = wc * 32 + nt * 8 + rin;
            int c  = kb * 4 + sel;
            b_off[nt][kb] = (u32)(rr * 128 + ((u32)(c ^ (rr & 7)) << 4));
        }

    const __half* xhb = g_xh + ((size_t)b * Nn + i0) * FIN;

    float acc[2][4][4];
    #pragma unroll
    for (int mt = 0; mt < 2; mt++)
        #pragma unroll
        for (int nt = 0; nt < 4; nt++)
            #pragma unroll
            for (int e = 0; e < 4; e++) acc[mt][nt][e] = 0.f;

    #define K1_ISSUE(c_, buf_) do {                                        \
        const int _k0 = (c_) * 64;                                         \
        const u32 _ab = sb + K1_A + (buf_) * 8192;                         \
        _Pragma("unroll")                                                  \
        for (int q = 0; q < 2; q++) {                                      \
            int flat = t + 256 * q;          /* 0..511 */                  \
            int row  = flat >> 3;                                          \
            int jc   = flat & 7;                                           \
            u32 sidx = (u32)(row * 128 + (((u32)(jc ^ (row & 7))) << 4));  \
            CP_ASYNC16(_ab + sidx, xhb + (size_t)row * FIN + _k0 + jc * 8);\
        }                                                                   \
        const u32 _bb = sb + K1_B + (buf_) * 16384;                        \
        _Pragma("unroll")                                                  \
        for (int q = 0; q < 4; q++) {                                      \
            int flat = t + 256 * q;          /* 0..1023 */                 \
            int row  = flat >> 3;                                          \
            int jc   = flat & 7;                                           \
            u32 sidx = (u32)(row * 128 + (((u32)(jc ^ (row & 7))) << 4));  \
            CP_ASYNC16(_bb + sidx,                                         \
                       g_Wt16 + (size_t)row * FIN + _k0 + jc * 8);         \
        }                                                                   \
        CP_COMMIT();                                                        \
    } while (0)

    K1_ISSUE(0, 0);
    CP_WAIT0();
    __syncthreads();

    for (int c = 0; c < 4; c++) {
        const int s = c & 1;
        if (c < 3) K1_ISSUE(c + 1, s ^ 1);

        const u32 ab = sb + K1_A + s * 8192;
        const u32 bb = sb + K1_B + s * 16384;
        #pragma unroll
        for (int kb = 0; kb < 2; kb++) {
            u32 bfr[4][4];
            #pragma unroll
            for (int nt = 0; nt < 4; nt++)
                ldmx4(bfr[nt], bb + b_off[nt][kb]);
            #pragma unroll
            for (int h = 0; h < 2; h++) {
                u32 afr[2][4];
                ldmx4(afr[0], ab + a_off[0][kb * 2 + h]);
                ldmx4(afr[1], ab + a_off[1][kb * 2 + h]);
                #pragma unroll
                for (int nt = 0; nt < 4; nt++) {
                    mma16816(acc[0][nt], afr[0], &bfr[nt][h * 2]);
                    mma16816(acc[1][nt], afr[1], &bfr[nt][h * 2]);
                }
            }
        }

        CP_WAIT0();
        __syncthreads();
    }

    // transpose epilogue: tr[128 f][72 halves]
    __half* tr = (__half*)dsm;
    #pragma unroll
    for (int mt = 0; mt < 2; mt++)
        #pragma unroll
        for (int nt = 0; nt < 4; nt++)
            #pragma unroll
            for (int h = 0; h < 2; h++)
                #pragma unroll
                for (int e = 0; e < 2; e++) {
                    int f = wc * 32 + nt * 8 + cl * 2 + e;
                    int j = wr * 32 + mt * 16 + g + 8 * h;
                    tr[(size_t)f * 72 + j] = __float2half(acc[mt][nt][h * 2 + e]);
                }
    __syncthreads();

    // coalesced store: thread -> f = t>>1, 32 j's
    {
        const int f   = t >> 1;
        const int seg = (t & 1) * 32;
        const __half* trow = tr + (size_t)f * 72 + seg;
        __half* dst = g_WhT + ((size_t)(b * FOUT + f)) * Nn + i0 + seg;
        #pragma unroll
        for (int m = 0; m < 4; m++)
            *(uint4*)(dst + m * 8) = *(const uint4*)(trow + m * 8);
    }
}

// ============================================================
// Kernel 1b: per-batch max of g_Ej (for fp16 range scaling)
// ============================================================
__global__ __launch_bounds__(256) void gat_maxe()
{
    const int b = blockIdx.x;
    const int t = threadIdx.x;
    float m = 0.f;
    #pragma unroll
    for (int q = 0; q < 8; q++)
        m = fmaxf(m, g_Ej[(size_t)b * Nn + t + 256 * q]);
    #pragma unroll
    for (int o = 16; o > 0; o >>= 1)
        m = fmaxf(m, __shfl_xor_sync(0xffffffffu, m, o));
    __shared__ float sm[8];
    if ((t & 31) == 0) sm[t >> 5] = m;
    __syncthreads();
    if (t == 0) {
        float r = sm[0];
        #pragma unroll
        for (int w = 1; w < 8; w++) r = fmaxf(r, sm[w]);
        g_maxE2[b] = r;
    }
}

// ============================================================
// Kernel 2: fused attention (unchanged from R11-passing version).
// ============================================================
#define SM_PS   0                        // 2 * 64*128B  = 16384
#define SM_WS   16384                    // 2 * 128*128B = 32768
#define SM_RS   49152                    // 64 floats
#define SM_TOT  49408

__global__ __launch_bounds__(256, 2) void gat_attn(
    const int* __restrict__ adj, float* __restrict__ out)
{
    extern __shared__ __align__(16) char dsm[];
    float* rows = (float*)(dsm + SM_RS);
    const u32 sb = smem_u32(dsm);

    const int t    = threadIdx.x;
    const int lane = t & 31;
    const int wid  = t >> 5;
    const int wr   = wid & 1;
    const int wc   = wid >> 1;
    const int g    = lane >> 2;
    const int cl   = lane & 3;
    const int b    = blockIdx.y;
    const int i0   = blockIdx.x * 64;

    const int sel = lane >> 3, rin = lane & 7;
    u32 a_off[2][4], b_off[4][2];
    #pragma unroll
    for (int mt = 0; mt < 2; mt++)
        #pragma unroll
        for (int ks = 0; ks < 4; ks++) {
            int r = wr * 32 + mt * 16 + ((sel & 1) << 3) + rin;
            int c = ks * 2 + (sel >> 1);
            a_off[mt][ks] = (u32)(r * 128 + ((u32)(c ^ (r & 7)) << 4));
        }
    #pragma unroll
    for (int nt = 0; nt < 4; nt++)
        #pragma unroll
        for (int kb = 0; kb < 2; kb++) {
            int rr = wc * 32 + nt * 8 + rin;
            int c  = kb * 4 + sel;
            b_off[nt][kb] = (u32)(rr * 128 + ((u32)(c ^ (rr & 7)) << 4));
        }

    const int iL = t >> 2;
    const int jq = t & 3;
    const int jh = jq * 16;
    u32 pst[2];
    #pragma unroll
    for (int q = 0; q < 2; q++)
        pst[q] = (u32)(iL * 128 + (((u32)((jq * 2 + q) ^ (iL & 7))) << 4));

    const float c1  = g_Ei[(size_t)b * Nn + i0 + iL];
    const float mE2 = g_maxE2[b];
    const float thrE = 1.0f / c1;
    float pm = c1 * mE2;
    pm = (pm >= 1.f) ? pm : pm * pm;
    int ex = (int)((__float_as_uint(pm) >> 23) & 255u) - 127;
    int kk = ex - 11; if (kk < 0) kk = 0;
    const float scale = __uint_as_float((u32)(127 - kk) << 23);
    const float c1s = c1 * scale;
    const float c2s = c1 * c1 * scale;

    const int*   arow = adj  + ((size_t)(b * Nn + i0 + iL)) * Nn + jh;
    const float* Ejb  = g_Ej + (size_t)b * Nn + jh;
    const __half* whtb = g_WhT + (size_t)b * FOUT * Nn;

    float acc[2][4][4];
    #pragma unroll
    for (int mt = 0; mt < 2; mt++)
        #pragma unroll
        for (int nt = 0; nt < 4; nt++)
            #pragma unroll
            for (int e = 0; e < 4; e++) acc[mt][nt][e] = 0.f;

    int4   sav[4];
    float4 sev[4];
    float  rs = 0.f;

    #define ISSUE_G(c_) do {                                              \
        const int _j0 = (c_) * CH;                                        \
        _Pragma("unroll")                                                 \
        for (int q = 0; q < 4; q++) {                                     \
            sav[q] = *(const int4*)&arow[_j0 + q * 4];                    \
            sev[q] = *(const float4*)&Ejb[_j0 + q * 4];                   \
        }                                                                  \
    } while (0)

    #define ISSUE_W(c_, buf_) do {                                        \
        const int _j0 = (c_) * CH;                                        \
        const u32 _wb = sb + SM_WS + (buf_) * 16384;                      \
        _Pragma("unroll")                                                 \
        for (int q = 0; q < 4; q++) {                                     \
            int flat = t + 256 * q;                                       \
            int row  = flat >> 3;                                         \
            int jc   = flat & 7;                                          \
            u32 sidx = (u32)(row * 128 + (((u32)(jc ^ (row & 7))) << 4)); \
            CP_ASYNC16(_wb + sidx,                                        \
                       &whtb[(size_t)row * Nn + _j0 + jc * 8]);           \
        }                                                                  \
        CP_COMMIT();                                                       \
    } while (0)

    #define FINISH(buf_) do {                                              \
        const int*   _a = (const int*)sav;                                 \
        const float* _e = (const float*)sev;                               \
        _Pragma("unroll")                                                   \
        for (int q = 0; q < 2; q++) {                                       \
            uint4 pv; u32* pw = (u32*)&pv;                                  \
            _Pragma("unroll")                                               \
            for (int u = 0; u < 4; u++) {                                   \
                int i2 = q * 8 + u * 2;                                     \
                float E0 = _e[i2], E1 = _e[i2 + 1];                         \
                float m0 = (E0 >= thrE) ? c1s : c2s * E0;                   \
                float m1 = (E1 >= thrE) ? c1s : c2s * E1;                   \
                float p0 = (_a[i2]     > 0) ? m0 * E0 : 0.f;                \
                float p1 = (_a[i2 + 1] > 0) ? m1 * E1 : 0.f;                \
                u32 h2 = pkh2(p0, p1);                                      \
                pw[u] = h2;                                                 \
                rs += __half2float(((const __half2*)&h2)->x)                \
                    + __half2float(((const __half2*)&h2)->y);               \
            }                                                                \
            *(uint4*)(dsm + SM_PS + (buf_) * 8192 + pst[q]) = pv;           \
        }                                                                    \
    } while (0)

    ISSUE_W(0, 0);
    ISSUE_G(0);
    FINISH(0);
    CP_WAIT0();
    __syncthreads();

    for (int c = 0; c < NCH; c++) {
        const int s = c & 1;
        if (c < NCH - 1) { ISSUE_G(c + 1); ISSUE_W(c + 1, s ^ 1); }

        {
            const u32 pb = sb + SM_PS + s * 8192;
            const u32 wb = sb + SM_WS + s * 16384;
            #pragma unroll
            for (int kb = 0; kb < 2; kb++) {
                u32 bfr[4][4];
                #pragma unroll
                for (int nt = 0; nt < 4; nt++)
                    ldmx4(bfr[nt], wb + b_off[nt][kb]);
                #pragma unroll
                for (int h = 0; h < 2; h++) {
                    u32 afr[2][4];
                    ldmx4(afr[0], pb + a_off[0][kb * 2 + h]);
                    ldmx4(afr[1], pb + a_off[1][kb * 2 + h]);
                    #pragma unroll
                    for (int nt = 0; nt < 4; nt++) {
                        mma16816(acc[0][nt], afr[0], &bfr[nt][h * 2]);
                        mma16816(acc[1][nt], afr[1], &bfr[nt][h * 2]);
                    }
                }
            }
        }

        if (c < NCH - 1) FINISH(s ^ 1);
        CP_WAIT0();
        __syncthreads();
    }

    rs += __shfl_xor_sync(0xffffffffu, rs, 1);
    rs += __shfl_xor_sync(0xffffffffu, rs, 2);
    if ((t & 3) == 0) rows[iL] = rs;
    __syncthreads();

    #pragma unroll
    for (int mt = 0; mt < 2; mt++)
        #pragma unroll
        for (int h = 0; h < 2; h++) {
            const int row = wr * 32 + mt * 16 + g + h * 8;
            const float inv = 1.0f / rows[row];
            float* orow = out + ((size_t)(b * Nn + i0 + row)) * FOUT + wc * 32 + cl * 2;
            #pragma unroll
            for (int nt = 0; nt < 4; nt++) {
                float h0 = acc[mt][nt][h * 2 + 0] * inv;
                float h1 = acc[mt][nt][h * 2 + 1] * inv;
                h0 = (h0 > 0.f) ? h0 : expm1f(h0);
                h1 = (h1 > 0.f) ? h1 : expm1f(h1);
                float2 o = make_float2(h0, h1);
                *(float2*)&orow[nt * 8] = o;
            }
        }
}

// ============================================================
extern "C" void kernel_launch(void* const* d_in, const int* in_sizes, int n_in,
                              void* d_out, int out_size)
{
    const float* x   = (const float*)d_in[0];   // [8,2048,256] f32
    const int*   adj = (const int*)  d_in[1];   // [8,2048,2048] i32
    const float* W   = (const float*)d_in[2];   // [256,128] f32
    const float* a   = (const float*)d_in[3];   // [256,1] f32
    float*       out = (float*)d_out;           // [8,2048,128] f32

    gat_prep<<<8, 256>>>(W, a);

    gat_xcvt<<<(Bb * Nn) / 64, 256>>>(x);

    gat_maxe<<<Bb, 256>>>();

    cudaFuncSetAttribute(gat_gemm_wh, cudaFuncAttributeMaxDynamicSharedMemorySize, K1_TOT);
    cudaFuncSetAttribute(gat_attn,    cudaFuncAttributeMaxDynamicSharedMemorySize, SM_TOT);

    dim3 g1(Nn / 64, Bb);
    gat_gemm_wh<<<g1, 256, K1_TOT>>>();

    dim3 g2(Nn / 64, Bb);
    gat_attn<<<g2, 256, SM_TOT>>>(adj, out);
}

// round 13
// speedup vs baseline: 1.3417x; 1.1355x over previous
#include <cuda_runtime.h>
#include <cuda_fp16.h>
#include <math.h>
#include <stdint.h>

#define Bb   8
#define Nn   2048
#define FIN  256
#define FOUT 128
#define CH   64          // attn j-chunk (128-byte fp16 rows)
#define NCH  (Nn / CH)   // 32

typedef unsigned long long u64;
typedef unsigned int u32;

// Scratch (device globals: allocation-free rule)
__device__ __half g_WhT[Bb * FOUT * Nn];   // [b][f][j], fp16
__device__ __half g_Wt16[FOUT * FIN];      // [f][k], fp16 W^T
__device__ float  g_va1[FIN];              // W @ a1
__device__ float  g_va2[FIN];              // W @ a2
__device__ float  g_Ei[Bb * Nn];           // exp(f1) per i-node
__device__ float  g_Ej[Bb * Nn];           // exp(f2) per j-node
__device__ int    g_maxE2i[Bb];            // per-batch max of g_Ej (float bits)

// ---------------- helpers ----------------
__forceinline__ __device__ u32 pkh2(float lo, float hi) {   // lo -> low half
    u32 r; asm("cvt.rn.f16x2.f32 %0,%1,%2;" : "=r"(r) : "f"(hi), "f"(lo)); return r;
}
__forceinline__ __device__ u32 smem_u32(const void* p) {
    u32 a;
    asm("{ .reg .u64 t; cvta.to.shared.u64 t,%1; cvt.u32.u64 %0,t; }" : "=r"(a) : "l"(p));
    return a;
}
__forceinline__ __device__ void mma16816(float* d, const u32* a, const u32* b) {
    asm volatile(
        "mma.sync.aligned.m16n8k16.row.col.f32.f16.f16.f32 "
        "{%0,%1,%2,%3},{%4,%5,%6,%7},{%8,%9},{%0,%1,%2,%3};"
        : "+f"(d[0]), "+f"(d[1]), "+f"(d[2]), "+f"(d[3])
        : "r"(a[0]), "r"(a[1]), "r"(a[2]), "r"(a[3]), "r"(b[0]), "r"(b[1]));
}
__forceinline__ __device__ void ldmx4(u32* d, u32 addr) {
    asm volatile("ldmatrix.sync.aligned.m8n8.x4.shared.b16 {%0,%1,%2,%3},[%4];"
        : "=r"(d[0]), "=r"(d[1]), "=r"(d[2]), "=r"(d[3]) : "r"(addr));
}
#define CP_ASYNC16(sdst, gsrc) \
    asm volatile("cp.async.cg.shared.global [%0], [%1], 16;" :: "r"(sdst), "l"(gsrc))
#define CP_COMMIT()  asm volatile("cp.async.commit_group;" ::: "memory")
#define CP_WAIT0()   asm volatile("cp.async.wait_group 0;" ::: "memory")

// ============================================================
// Kernel 0: prep — va1 = W@a1, va2 = W@a2 (fp32), Wt16 = W^T fp16.
// ============================================================
__global__ __launch_bounds__(256) void gat_prep(
    const float* __restrict__ W, const float* __restrict__ a)
{
    const int t = threadIdx.x, bid = blockIdx.x;
    if (bid == 0) {
        float s1 = 0.f, s2 = 0.f;
        #pragma unroll 8
        for (int f = 0; f < FOUT; f++) {
            float w = W[(size_t)t * FOUT + f];
            s1 += w * a[f];
            s2 += w * a[FOUT + f];
        }
        g_va1[t] = s1; g_va2[t] = s2;
    }
    const int f  = bid * 16 + (t >> 4);
    const int k0 = (t & 15) * 16;
    __half* dst = g_Wt16 + (size_t)f * FIN + k0;
    #pragma unroll
    for (int k = 0; k < 16; k++)
        dst[k] = __float2half(W[(size_t)(k0 + k) * FOUT + f]);
}

// ============================================================
// Kernel 1: fused Wh = x@W (fp16 MMA) + f1/f2 (fp32) + exp + maxE2.
// CTA: 64 i x 128 f, K chunks of 64. A built in-kernel from fp32 x
// (conversion overlapped with MMA); B via cp.async double buffer.
// Epilogue: smem transpose -> WhT fp16; Ei/Ej + atomicMax.
// ============================================================
#define K1_A   0            // 2 x 64 rows x 128 B  = 16384
#define K1_B   16384        // 2 x 128 rows x 128 B = 32768
#define K1_VA  49152        // 2 x 256 floats       = 2048
#define K1_TOT 51200

__global__ __launch_bounds__(256, 2) void gat_gemm_wh(const float* __restrict__ x)
{
    extern __shared__ __align__(16) char dsm[];
    const u32 sb = smem_u32(dsm);
    float* va1s = (float*)(dsm + K1_VA);
    float* va2s = (float*)(dsm + K1_VA + 1024);

    const int t    = threadIdx.x;
    const int lane = t & 31;
    const int wid  = t >> 5;
    const int wr   = wid & 1;           // 32-row half of 64 i
    const int wc   = wid >> 1;          // 32-col group of 128 f
    const int g    = lane >> 2;
    const int cl   = lane & 3;
    const int sel  = lane >> 3, rin = lane & 7;
    const int b    = blockIdx.y;
    const int i0   = blockIdx.x * 64;

    va1s[t] = g_va1[t];
    va2s[t] = g_va2[t];

    // fragment offsets (validated scheme)
    u32 a_off[2][4], b_off[4][2];
    #pragma unroll
    for (int mt = 0; mt < 2; mt++)
        #pragma unroll
        for (int ks = 0; ks < 4; ks++) {
            int r = wr * 32 + mt * 16 + ((sel & 1) << 3) + rin;
            int c = ks * 2 + (sel >> 1);
            a_off[mt][ks] = (u32)(r * 128 + ((u32)(c ^ (r & 7)) << 4));
        }
    #pragma unroll
    for (int nt = 0; nt < 4; nt++)
        #pragma unroll
        for (int kb = 0; kb < 2; kb++) {
            int rr = wc * 32 + nt * 8 + rin;
            int c  = kb * 4 + sel;
            b_off[nt][kb] = (u32)(rr * 128 + ((u32)(c ^ (rr & 7)) << 4));
        }

    // A-build mapping: row = t>>2 (64 rows), 16 k-halves at kseg
    const int row  = t >> 2;
    const int kseg = (t & 3) * 16;
    const float* xb = x + ((size_t)b * Nn + i0 + row) * FIN + kseg;

    float acc[2][4][4];
    #pragma unroll
    for (int mt = 0; mt < 2; mt++)
        #pragma unroll
        for (int nt = 0; nt < 4; nt++)
            #pragma unroll
            for (int e = 0; e < 4; e++) acc[mt][nt][e] = 0.f;

    float4 xr[4];
    float  f1p = 0.f, f2p = 0.f;

    #define LDX(c_) do {                                                   \
        const float* _p = xb + (c_) * 64;                                  \
        xr[0] = *(const float4*)(_p);                                      \
        xr[1] = *(const float4*)(_p + 4);                                  \
        xr[2] = *(const float4*)(_p + 8);                                  \
        xr[3] = *(const float4*)(_p + 12);                                 \
    } while (0)

    #define BUILD_A(c_, buf_) do {                                         \
        const u32 _ab = sb + K1_A + (buf_) * 8192;                         \
        const int _kb = (c_) * 64 + kseg;                                  \
        _Pragma("unroll")                                                  \
        for (int q = 0; q < 4; q++) {                                      \
            float4 v1 = *(const float4*)&va1s[_kb + q * 4];                \
            float4 v2 = *(const float4*)&va2s[_kb + q * 4];                \
            f1p += xr[q].x*v1.x + xr[q].y*v1.y + xr[q].z*v1.z + xr[q].w*v1.w; \
            f2p += xr[q].x*v2.x + xr[q].y*v2.y + xr[q].z*v2.z + xr[q].w*v2.w; \
        }                                                                   \
        uint4 h0, h1;                                                       \
        h0.x = pkh2(xr[0].x, xr[0].y); h0.y = pkh2(xr[0].z, xr[0].w);      \
        h0.z = pkh2(xr[1].x, xr[1].y); h0.w = pkh2(xr[1].z, xr[1].w);      \
        h1.x = pkh2(xr[2].x, xr[2].y); h1.y = pkh2(xr[2].z, xr[2].w);      \
        h1.z = pkh2(xr[3].x, xr[3].y); h1.w = pkh2(xr[3].z, xr[3].w);      \
        u32 jc = (u32)((t & 3) * 2);                                        \
        *(uint4*)(dsm + K1_A + (buf_) * 8192 + row * 128                    \
                  + ((jc ^ (u32)(row & 7)) << 4)) = h0;                     \
        *(uint4*)(dsm + K1_A + (buf_) * 8192 + row * 128                    \
                  + (((jc + 1) ^ (u32)(row & 7)) << 4)) = h1;               \
        (void)_ab;                                                          \
    } while (0)

    #define ISSUE_B(c_, buf_) do {                                         \
        const int _k0 = (c_) * 64;                                         \
        const u32 _bb = sb + K1_B + (buf_) * 16384;                        \
        _Pragma("unroll")                                                  \
        for (int q = 0; q < 4; q++) {                                      \
            int flat = t + 256 * q;          /* 0..1023 */                 \
            int frow = flat >> 3;                                          \
            int jc2  = flat & 7;                                           \
            u32 sidx = (u32)(frow * 128 + (((u32)(jc2 ^ (frow & 7))) << 4)); \
            CP_ASYNC16(_bb + sidx,                                         \
                       g_Wt16 + (size_t)frow * FIN + _k0 + jc2 * 8);       \
        }                                                                   \
        CP_COMMIT();                                                        \
    } while (0)

    LDX(0);
    ISSUE_B(0, 0);
    __syncthreads();                    // va1s/va2s visible
    BUILD_A(0, 0);
    CP_WAIT0();
    __syncthreads();

    for (int c = 0; c < 4; c++) {
        const int s = c & 1;
        if (c < 3) { LDX(c + 1); ISSUE_B(c + 1, s ^ 1); }

        const u32 ab = sb + K1_A + s * 8192;
        const u32 bb = sb + K1_B + s * 16384;
        #pragma unroll
        for (int kb = 0; kb < 2; kb++) {
            u32 bfr[4][4];
            #pragma unroll
            for (int nt = 0; nt < 4; nt++)
                ldmx4(bfr[nt], bb + b_off[nt][kb]);
            #pragma unroll
            for (int h = 0; h < 2; h++) {
                u32 afr[2][4];
                ldmx4(afr[0], ab + a_off[0][kb * 2 + h]);
                ldmx4(afr[1], ab + a_off[1][kb * 2 + h]);
                #pragma unroll
                for (int nt = 0; nt < 4; nt++) {
                    mma16816(acc[0][nt], afr[0], &bfr[nt][h * 2]);
                    mma16816(acc[1][nt], afr[1], &bfr[nt][h * 2]);
                }
            }
        }

        if (c < 3) BUILD_A(c + 1, s ^ 1);
        CP_WAIT0();
        __syncthreads();
    }

    // f1/f2: reduce over the 4 k-segment threads of each row
    f1p += __shfl_xor_sync(0xffffffffu, f1p, 1);
    f1p += __shfl_xor_sync(0xffffffffu, f1p, 2);
    f2p += __shfl_xor_sync(0xffffffffu, f2p, 1);
    f2p += __shfl_xor_sync(0xffffffffu, f2p, 2);
    float E2 = 0.f;
    if ((t & 3) == 0) {
        size_t R = (size_t)b * Nn + i0 + row;
        float E1 = __expf(f1p);
        E2 = __expf(f2p);
        g_Ei[R] = E1;
        g_Ej[R] = E2;
    }
    // warp-max of E2 -> one atomic per warp
    float wm = E2;
    #pragma unroll
    for (int o = 16; o > 0; o >>= 1)
        wm = fmaxf(wm, __shfl_xor_sync(0xffffffffu, wm, o));
    if (lane == 0) atomicMax(&g_maxE2i[b], __float_as_int(wm));

    // transpose epilogue: tr[128 f][72 halves] (aliases A/B[0] region)
    __half* tr = (__half*)dsm;
    #pragma unroll
    for (int mt = 0; mt < 2; mt++)
        #pragma unroll
        for (int nt = 0; nt < 4; nt++)
            #pragma unroll
            for (int h = 0; h < 2; h++)
                #pragma unroll
                for (int e = 0; e < 2; e++) {
                    int f = wc * 32 + nt * 8 + cl * 2 + e;
                    int j = wr * 32 + mt * 16 + g + 8 * h;
                    tr[(size_t)f * 72 + j] = __float2half(acc[mt][nt][h * 2 + e]);
                }
    __syncthreads();

    // coalesced store: thread -> f = t>>1, 32 j's
    {
        const int f   = t >> 1;
        const int seg = (t & 1) * 32;
        const __half* trow = tr + (size_t)f * 72 + seg;
        __half* dst = g_WhT + ((size_t)(b * FOUT + f)) * Nn + i0 + seg;
        #pragma unroll
        for (int m = 0; m < 4; m++)
            *(uint4*)(dst + m * 8) = *(const uint4*)(trow + m * 8);
    }
}

// ============================================================
// Kernel 2: fused attention (R11-passing version; rs trimmed to
// pre-rounded fp32 accumulation — drops 32 h2f converts/chunk/thread).
// ============================================================
#define SM_PS   0                        // 2 * 64*128B  = 16384
#define SM_WS   16384                    // 2 * 128*128B = 32768
#define SM_RS   49152                    // 64 floats
#define SM_TOT  49408

__global__ __launch_bounds__(256, 2) void gat_attn(
    const int* __restrict__ adj, float* __restrict__ out)
{
    extern __shared__ __align__(16) char dsm[];
    float* rows = (float*)(dsm + SM_RS);
    const u32 sb = smem_u32(dsm);

    const int t    = threadIdx.x;
    const int lane = t & 31;
    const int wid  = t >> 5;
    const int wr   = wid & 1;
    const int wc   = wid >> 1;
    const int g    = lane >> 2;
    const int cl   = lane & 3;
    const int b    = blockIdx.y;
    const int i0   = blockIdx.x * 64;

    const int sel = lane >> 3, rin = lane & 7;
    u32 a_off[2][4], b_off[4][2];
    #pragma unroll
    for (int mt = 0; mt < 2; mt++)
        #pragma unroll
        for (int ks = 0; ks < 4; ks++) {
            int r = wr * 32 + mt * 16 + ((sel & 1) << 3) + rin;
            int c = ks * 2 + (sel >> 1);
            a_off[mt][ks] = (u32)(r * 128 + ((u32)(c ^ (r & 7)) << 4));
        }
    #pragma unroll
    for (int nt = 0; nt < 4; nt++)
        #pragma unroll
        for (int kb = 0; kb < 2; kb++) {
            int rr = wc * 32 + nt * 8 + rin;
            int c  = kb * 4 + sel;
            b_off[nt][kb] = (u32)(rr * 128 + ((u32)(c ^ (rr & 7)) << 4));
        }

    const int iL = t >> 2;
    const int jq = t & 3;
    const int jh = jq * 16;
    u32 pst[2];
    #pragma unroll
    for (int q = 0; q < 2; q++)
        pst[q] = (u32)(iL * 128 + (((u32)((jq * 2 + q) ^ (iL & 7))) << 4));

    const float c1  = g_Ei[(size_t)b * Nn + i0 + iL];
    const float mE2 = __int_as_float(g_maxE2i[b]);
    const float thrE = 1.0f / c1;
    float pm = c1 * mE2;
    pm = (pm >= 1.f) ? pm : pm * pm;
    int ex = (int)((__float_as_uint(pm) >> 23) & 255u) - 127;
    int kk = ex - 11; if (kk < 0) kk = 0;
    const float scale = __uint_as_float((u32)(127 - kk) << 23);
    const float c1s = c1 * scale;
    const float c2s = c1 * c1 * scale;

    const int*   arow = adj  + ((size_t)(b * Nn + i0 + iL)) * Nn + jh;
    const float* Ejb  = g_Ej + (size_t)b * Nn + jh;
    const __half* whtb = g_WhT + (size_t)b * FOUT * Nn;

    float acc[2][4][4];
    #pragma unroll
    for (int mt = 0; mt < 2; mt++)
        #pragma unroll
        for (int nt = 0; nt < 4; nt++)
            #pragma unroll
            for (int e = 0; e < 4; e++) acc[mt][nt][e] = 0.f;

    int4   sav[4];
    float4 sev[4];
    float  rs = 0.f;

    #define ISSUE_G(c_) do {                                              \
        const int _j0 = (c_) * CH;                                        \
        _Pragma("unroll")                                                 \
        for (int q = 0; q < 4; q++) {                                     \
            sav[q] = *(const int4*)&arow[_j0 + q * 4];                    \
            sev[q] = *(const float4*)&Ejb[_j0 + q * 4];                   \
        }                                                                  \
    } while (0)

    #define ISSUE_W(c_, buf_) do {                                        \
        const int _j0 = (c_) * CH;                                        \
        const u32 _wb = sb + SM_WS + (buf_) * 16384;                      \
        _Pragma("unroll")                                                 \
        for (int q = 0; q < 4; q++) {                                     \
            int flat = t + 256 * q;                                       \
            int row  = flat >> 3;                                         \
            int jc   = flat & 7;                                          \
            u32 sidx = (u32)(row * 128 + (((u32)(jc ^ (row & 7))) << 4)); \
            CP_ASYNC16(_wb + sidx,                                        \
                       &whtb[(size_t)row * Nn + _j0 + jc * 8]);           \
        }                                                                  \
        CP_COMMIT();                                                       \
    } while (0)

    #define FINISH(buf_) do {                                              \
        const int*   _a = (const int*)sav;                                 \
        const float* _e = (const float*)sev;                               \
        _Pragma("unroll")                                                   \
        for (int q = 0; q < 2; q++) {                                       \
            uint4 pv; u32* pw = (u32*)&pv;                                  \
            _Pragma("unroll")                                               \
            for (int u = 0; u < 4; u++) {                                   \
                int i2 = q * 8 + u * 2;                                     \
                float E0 = _e[i2], E1 = _e[i2 + 1];                         \
                float m0 = (E0 >= thrE) ? c1s : c2s * E0;                   \
                float m1 = (E1 >= thrE) ? c1s : c2s * E1;                   \
                float p0 = (_a[i2]     > 0) ? m0 * E0 : 0.f;                \
                float p1 = (_a[i2 + 1] > 0) ? m1 * E1 : 0.f;                \
                pw[u] = pkh2(p0, p1);                                       \
                rs += p0 + p1;                                              \
            }                                                                \
            *(uint4*)(dsm + SM_PS + (buf_) * 8192 + pst[q]) = pv;           \
        }                                                                    \
    } while (0)

    ISSUE_W(0, 0);
    ISSUE_G(0);
    FINISH(0);
    CP_WAIT0();
    __syncthreads();

    for (int c = 0; c < NCH; c++) {
        const int s = c & 1;
        if (c < NCH - 1) { ISSUE_G(c + 1); ISSUE_W(c + 1, s ^ 1); }

        {
            const u32 pb = sb + SM_PS + s * 8192;
            const u32 wb = sb + SM_WS + s * 16384;
            #pragma unroll
            for (int kb = 0; kb < 2; kb++) {
                u32 bfr[4][4];
                #pragma unroll
                for (int nt = 0; nt < 4; nt++)
                    ldmx4(bfr[nt], wb + b_off[nt][kb]);
                #pragma unroll
                for (int h = 0; h < 2; h++) {
                    u32 afr[2][4];
                    ldmx4(afr[0], pb + a_off[0][kb * 2 + h]);
                    ldmx4(afr[1], pb + a_off[1][kb * 2 + h]);
                    #pragma unroll
                    for (int nt = 0; nt < 4; nt++) {
                        mma16816(acc[0][nt], afr[0], &bfr[nt][h * 2]);
                        mma16816(acc[1][nt], afr[1], &bfr[nt][h * 2]);
                    }
                }
            }
        }

        if (c < NCH - 1) FINISH(s ^ 1);
        CP_WAIT0();
        __syncthreads();
    }

    rs += __shfl_xor_sync(0xffffffffu, rs, 1);
    rs += __shfl_xor_sync(0xffffffffu, rs, 2);
    if ((t & 3) == 0) rows[iL] = rs;
    __syncthreads();

    #pragma unroll
    for (int mt = 0; mt < 2; mt++)
        #pragma unroll
        for (int h = 0; h < 2; h++) {
            const int row = wr * 32 + mt * 16 + g + h * 8;
            const float inv = 1.0f / rows[row];
            float* orow = out + ((size_t)(b * Nn + i0 + row)) * FOUT + wc * 32 + cl * 2;
            #pragma unroll
            for (int nt = 0; nt < 4; nt++) {
                float h0 = acc[mt][nt][h * 2 + 0] * inv;
                float h1 = acc[mt][nt][h * 2 + 1] * inv;
                h0 = (h0 > 0.f) ? h0 : expm1f(h0);
                h1 = (h1 > 0.f) ? h1 : expm1f(h1);
                float2 o = make_float2(h0, h1);
                *(float2*)&orow[nt * 8] = o;
            }
        }
}

// ============================================================
extern "C" void kernel_launch(void* const* d_in, const int* in_sizes, int n_in,
                              void* d_out, int out_size)
{
    const float* x   = (const float*)d_in[0];   // [8,2048,256] f32
    const int*   adj = (const int*)  d_in[1];   // [8,2048,2048] i32
    const float* W   = (const float*)d_in[2];   // [256,128] f32
    const float* a   = (const float*)d_in[3];   // [256,1] f32
    float*       out = (float*)d_out;           // [8,2048,128] f32

    gat_prep<<<8, 256>>>(W, a);

    cudaFuncSetAttribute(gat_gemm_wh, cudaFuncAttributeMaxDynamicSharedMemorySize, K1_TOT);
    cudaFuncSetAttribute(gat_attn,    cudaFuncAttributeMaxDynamicSharedMemorySize, SM_TOT);

    dim3 g1(Nn / 64, Bb);
    gat_gemm_wh<<<g1, 256, K1_TOT>>>(x);

    dim3 g2(Nn / 64, Bb);
    gat_attn<<<g2, 256, SM_TOT>>>(adj, out);
}

// round 14
// speedup vs baseline: 1.6448x; 1.2259x over previous
#include <cuda_runtime.h>
#include <cuda_fp16.h>
#include <math.h>
#include <stdint.h>

#define Bb   8
#define Nn   2048
#define FIN  256
#define FOUT 128
#define CH   64          // attn j-chunk (128-byte fp16 rows)
#define NCH  (Nn / CH)   // 32

typedef unsigned long long u64;
typedef unsigned int u32;

// Scratch (device globals: allocation-free rule)
__device__ __half g_WhT[Bb * FOUT * Nn];   // [b][f][j], fp16
__device__ __half g_Wt16[FOUT * FIN];      // [f][k], fp16 W^T
__device__ float  g_va1[FIN];              // W @ a1
__device__ float  g_va2[FIN];              // W @ a2
__device__ float  g_Ei[Bb * Nn];           // exp(f1) per i-node
__device__ float  g_Ej[Bb * Nn];           // exp(f2) per j-node
__device__ int    g_maxE2i[Bb];            // per-batch max of g_Ej (float bits)

// ---------------- helpers ----------------
__forceinline__ __device__ u32 pkh2(float lo, float hi) {   // lo -> low half
    u32 r; asm("cvt.rn.f16x2.f32 %0,%1,%2;" : "=r"(r) : "f"(hi), "f"(lo)); return r;
}
__forceinline__ __device__ u32 smem_u32(const void* p) {
    u32 a;
    asm("{ .reg .u64 t; cvta.to.shared.u64 t,%1; cvt.u32.u64 %0,t; }" : "=r"(a) : "l"(p));
    return a;
}
__forceinline__ __device__ void mma16816(float* d, const u32* a, const u32* b) {
    asm volatile(
        "mma.sync.aligned.m16n8k16.row.col.f32.f16.f16.f32 "
        "{%0,%1,%2,%3},{%4,%5,%6,%7},{%8,%9},{%0,%1,%2,%3};"
        : "+f"(d[0]), "+f"(d[1]), "+f"(d[2]), "+f"(d[3])
        : "r"(a[0]), "r"(a[1]), "r"(a[2]), "r"(a[3]), "r"(b[0]), "r"(b[1]));
}
__forceinline__ __device__ void ldmx4(u32* d, u32 addr) {
    asm volatile("ldmatrix.sync.aligned.m8n8.x4.shared.b16 {%0,%1,%2,%3},[%4];"
        : "=r"(d[0]), "=r"(d[1]), "=r"(d[2]), "=r"(d[3]) : "r"(addr));
}
#define CP_ASYNC16(sdst, gsrc) \
    asm volatile("cp.async.cg.shared.global [%0], [%1], 16;" :: "r"(sdst), "l"(gsrc))
#define CP_COMMIT()  asm volatile("cp.async.commit_group;" ::: "memory")
#define CP_WAIT0()   asm volatile("cp.async.wait_group 0;" ::: "memory")

// ============================================================
// Kernel 0: prep — coalesced W transpose + va1/va2.
// Grid 8: CTA owns 32 k-rows. Load 32x128 fp32 coalesced -> smem,
// compute va (8 thr/k, shfl), write Wt16 fp16 from transpose.
// ============================================================
__global__ __launch_bounds__(256) void gat_prep(
    const float* __restrict__ W, const float* __restrict__ a)
{
    __shared__ float ws[32][129];
    __shared__ float as[2 * FOUT];
    const int t  = threadIdx.x;
    const int k0 = blockIdx.x * 32;

    as[t] = a[t];
    #pragma unroll
    for (int it = 0; it < 16; it++) {
        int flat = t + 256 * it;          // 0..4095
        int kr   = flat >> 7;             // 0..31
        int f    = flat & 127;
        ws[kr][f] = W[(size_t)(k0 + kr) * FOUT + f];
    }
    __syncthreads();

    // va1/va2: 8 threads per k-row
    {
        const int kr = t >> 3;
        const int f0 = (t & 7) * 16;
        float s1 = 0.f, s2 = 0.f;
        #pragma unroll
        for (int u = 0; u < 16; u++) {
            float w = ws[kr][f0 + u];
            s1 += w * as[f0 + u];
            s2 += w * as[FOUT + f0 + u];
        }
        #pragma unroll
        for (int o = 4; o > 0; o >>= 1) {
            s1 += __shfl_xor_sync(0xffffffffu, s1, o);
            s2 += __shfl_xor_sync(0xffffffffu, s2, o);
        }
        if ((t & 7) == 0) { g_va1[k0 + kr] = s1; g_va2[k0 + kr] = s2; }
    }

    // Wt16 write: thread -> f = t>>1, 16 k's at kh
    {
        const int f  = t >> 1;
        const int kh = (t & 1) * 16;
        u32 hb[8];
        #pragma unroll
        for (int u = 0; u < 8; u++)
            hb[u] = pkh2(ws[kh + u * 2][f], ws[kh + u * 2 + 1][f]);
        __half* dst = g_Wt16 + (size_t)f * FIN + k0 + kh;
        *(uint4*)dst       = *(uint4*)&hb[0];
        *(uint4*)(dst + 8) = *(uint4*)&hb[4];
    }
}

// ============================================================
// Kernel 1: fused Wh = x@W (fp16 MMA) + f1/f2 (fp32) + exp + maxE2.
// (unchanged from R13-passing version)
// ============================================================
#define K1_A   0            // 2 x 64 rows x 128 B  = 16384
#define K1_B   16384        // 2 x 128 rows x 128 B = 32768
#define K1_VA  49152        // 2 x 256 floats       = 2048
#define K1_TOT 51200

__global__ __launch_bounds__(256, 2) void gat_gemm_wh(const float* __restrict__ x)
{
    extern __shared__ __align__(16) char dsm[];
    const u32 sb = smem_u32(dsm);
    float* va1s = (float*)(dsm + K1_VA);
    float* va2s = (float*)(dsm + K1_VA + 1024);

    const int t    = threadIdx.x;
    const int lane = t & 31;
    const int wid  = t >> 5;
    const int wr   = wid & 1;
    const int wc   = wid >> 1;
    const int g    = lane >> 2;
    const int cl   = lane & 3;
    const int sel  = lane >> 3, rin = lane & 7;
    const int b    = blockIdx.y;
    const int i0   = blockIdx.x * 64;

    va1s[t] = g_va1[t];
    va2s[t] = g_va2[t];

    u32 a_off[2][4], b_off[4][2];
    #pragma unroll
    for (int mt = 0; mt < 2; mt++)
        #pragma unroll
        for (int ks = 0; ks < 4; ks++) {
            int r = wr * 32 + mt * 16 + ((sel & 1) << 3) + rin;
            int c = ks * 2 + (sel >> 1);
            a_off[mt][ks] = (u32)(r * 128 + ((u32)(c ^ (r & 7)) << 4));
        }
    #pragma unroll
    for (int nt = 0; nt < 4; nt++)
        #pragma unroll
        for (int kb = 0; kb < 2; kb++) {
            int rr = wc * 32 + nt * 8 + rin;
            int c  = kb * 4 + sel;
            b_off[nt][kb] = (u32)(rr * 128 + ((u32)(c ^ (rr & 7)) << 4));
        }

    const int row  = t >> 2;
    const int kseg = (t & 3) * 16;
    const float* xb = x + ((size_t)b * Nn + i0 + row) * FIN + kseg;

    float acc[2][4][4];
    #pragma unroll
    for (int mt = 0; mt < 2; mt++)
        #pragma unroll
        for (int nt = 0; nt < 4; nt++)
            #pragma unroll
            for (int e = 0; e < 4; e++) acc[mt][nt][e] = 0.f;

    float4 xr[4];
    float  f1p = 0.f, f2p = 0.f;

    #define LDX(c_) do {                                                   \
        const float* _p = xb + (c_) * 64;                                  \
        xr[0] = *(const float4*)(_p);                                      \
        xr[1] = *(const float4*)(_p + 4);                                  \
        xr[2] = *(const float4*)(_p + 8);                                  \
        xr[3] = *(const float4*)(_p + 12);                                 \
    } while (0)

    #define BUILD_A(c_, buf_) do {                                         \
        const int _kb = (c_) * 64 + kseg;                                  \
        _Pragma("unroll")                                                  \
        for (int q = 0; q < 4; q++) {                                      \
            float4 v1 = *(const float4*)&va1s[_kb + q * 4];                \
            float4 v2 = *(const float4*)&va2s[_kb + q * 4];                \
            f1p += xr[q].x*v1.x + xr[q].y*v1.y + xr[q].z*v1.z + xr[q].w*v1.w; \
            f2p += xr[q].x*v2.x + xr[q].y*v2.y + xr[q].z*v2.z + xr[q].w*v2.w; \
        }                                                                   \
        uint4 h0, h1;                                                       \
        h0.x = pkh2(xr[0].x, xr[0].y); h0.y = pkh2(xr[0].z, xr[0].w);      \
        h0.z = pkh2(xr[1].x, xr[1].y); h0.w = pkh2(xr[1].z, xr[1].w);      \
        h1.x = pkh2(xr[2].x, xr[2].y); h1.y = pkh2(xr[2].z, xr[2].w);      \
        h1.z = pkh2(xr[3].x, xr[3].y); h1.w = pkh2(xr[3].z, xr[3].w);      \
        u32 jc = (u32)((t & 3) * 2);                                        \
        *(uint4*)(dsm + K1_A + (buf_) * 8192 + row * 128                    \
                  + ((jc ^ (u32)(row & 7)) << 4)) = h0;                     \
        *(uint4*)(dsm + K1_A + (buf_) * 8192 + row * 128                    \
                  + (((jc + 1) ^ (u32)(row & 7)) << 4)) = h1;               \
    } while (0)

    #define ISSUE_B(c_, buf_) do {                                         \
        const int _k0 = (c_) * 64;                                         \
        const u32 _bb = sb + K1_B + (buf_) * 16384;                        \
        _Pragma("unroll")                                                  \
        for (int q = 0; q < 4; q++) {                                      \
            int flat = t + 256 * q;                                        \
            int frow = flat >> 3;                                          \
            int jc2  = flat & 7;                                           \
            u32 sidx = (u32)(frow * 128 + (((u32)(jc2 ^ (frow & 7))) << 4)); \
            CP_ASYNC16(_bb + sidx,                                         \
                       g_Wt16 + (size_t)frow * FIN + _k0 + jc2 * 8);       \
        }                                                                   \
        CP_COMMIT();                                                        \
    } while (0)

    LDX(0);
    ISSUE_B(0, 0);
    __syncthreads();                    // va1s/va2s visible
    BUILD_A(0, 0);
    CP_WAIT0();
    __syncthreads();

    for (int c = 0; c < 4; c++) {
        const int s = c & 1;
        if (c < 3) { LDX(c + 1); ISSUE_B(c + 1, s ^ 1); }

        const u32 ab = sb + K1_A + s * 8192;
        const u32 bb = sb + K1_B + s * 16384;
        #pragma unroll
        for (int kb = 0; kb < 2; kb++) {
            u32 bfr[4][4];
            #pragma unroll
            for (int nt = 0; nt < 4; nt++)
                ldmx4(bfr[nt], bb + b_off[nt][kb]);
            #pragma unroll
            for (int h = 0; h < 2; h++) {
                u32 afr[2][4];
                ldmx4(afr[0], ab + a_off[0][kb * 2 + h]);
                ldmx4(afr[1], ab + a_off[1][kb * 2 + h]);
                #pragma unroll
                for (int nt = 0; nt < 4; nt++) {
                    mma16816(acc[0][nt], afr[0], &bfr[nt][h * 2]);
                    mma16816(acc[1][nt], afr[1], &bfr[nt][h * 2]);
                }
            }
        }

        if (c < 3) BUILD_A(c + 1, s ^ 1);
        CP_WAIT0();
        __syncthreads();
    }

    f1p += __shfl_xor_sync(0xffffffffu, f1p, 1);
    f1p += __shfl_xor_sync(0xffffffffu, f1p, 2);
    f2p += __shfl_xor_sync(0xffffffffu, f2p, 1);
    f2p += __shfl_xor_sync(0xffffffffu, f2p, 2);
    float E2 = 0.f;
    if ((t & 3) == 0) {
        size_t R = (size_t)b * Nn + i0 + row;
        float E1 = __expf(f1p);
        E2 = __expf(f2p);
        g_Ei[R] = E1;
        g_Ej[R] = E2;
    }
    float wm = E2;
    #pragma unroll
    for (int o = 16; o > 0; o >>= 1)
        wm = fmaxf(wm, __shfl_xor_sync(0xffffffffu, wm, o));
    if (lane == 0) atomicMax(&g_maxE2i[b], __float_as_int(wm));

    __half* tr = (__half*)dsm;
    #pragma unroll
    for (int mt = 0; mt < 2; mt++)
        #pragma unroll
        for (int nt = 0; nt < 4; nt++)
            #pragma unroll
            for (int h = 0; h < 2; h++)
                #pragma unroll
                for (int e = 0; e < 2; e++) {
                    int f = wc * 32 + nt * 8 + cl * 2 + e;
                    int j = wr * 32 + mt * 16 + g + 8 * h;
                    tr[(size_t)f * 72 + j] = __float2half(acc[mt][nt][h * 2 + e]);
                }
    __syncthreads();

    {
        const int f   = t >> 1;
        const int seg = (t & 1) * 32;
        const __half* trow = tr + (size_t)f * 72 + seg;
        __half* dst = g_WhT + ((size_t)(b * FOUT + f)) * Nn + i0 + seg;
        #pragma unroll
        for (int m = 0; m < 4; m++)
            *(uint4*)(dst + m * 8) = *(const uint4*)(trow + m * 8);
    }
}

// ============================================================
// Kernel 2: fused attention (unchanged from R13-passing version).
// ============================================================
#define SM_PS   0                        // 2 * 64*128B  = 16384
#define SM_WS   16384                    // 2 * 128*128B = 32768
#define SM_RS   49152                    // 64 floats
#define SM_TOT  49408

__global__ __launch_bounds__(256, 2) void gat_attn(
    const int* __restrict__ adj, float* __restrict__ out)
{
    extern __shared__ __align__(16) char dsm[];
    float* rows = (float*)(dsm + SM_RS);
    const u32 sb = smem_u32(dsm);

    const int t    = threadIdx.x;
    const int lane = t & 31;
    const int wid  = t >> 5;
    const int wr   = wid & 1;
    const int wc   = wid >> 1;
    const int g    = lane >> 2;
    const int cl   = lane & 3;
    const int b    = blockIdx.y;
    const int i0   = blockIdx.x * 64;

    const int sel = lane >> 3, rin = lane & 7;
    u32 a_off[2][4], b_off[4][2];
    #pragma unroll
    for (int mt = 0; mt < 2; mt++)
        #pragma unroll
        for (int ks = 0; ks < 4; ks++) {
            int r = wr * 32 + mt * 16 + ((sel & 1) << 3) + rin;
            int c = ks * 2 + (sel >> 1);
            a_off[mt][ks] = (u32)(r * 128 + ((u32)(c ^ (r & 7)) << 4));
        }
    #pragma unroll
    for (int nt = 0; nt < 4; nt++)
        #pragma unroll
        for (int kb = 0; kb < 2; kb++) {
            int rr = wc * 32 + nt * 8 + rin;
            int c  = kb * 4 + sel;
            b_off[nt][kb] = (u32)(rr * 128 + ((u32)(c ^ (rr & 7)) << 4));
        }

    const int iL = t >> 2;
    const int jq = t & 3;
    const int jh = jq * 16;
    u32 pst[2];
    #pragma unroll
    for (int q = 0; q < 2; q++)
        pst[q] = (u32)(iL * 128 + (((u32)((jq * 2 + q) ^ (iL & 7))) << 4));

    const float c1  = g_Ei[(size_t)b * Nn + i0 + iL];
    const float mE2 = __int_as_float(g_maxE2i[b]);
    const float thrE = 1.0f / c1;
    float pm = c1 * mE2;
    pm = (pm >= 1.f) ? pm : pm * pm;
    int ex = (int)((__float_as_uint(pm) >> 23) & 255u) - 127;
    int kk = ex - 11; if (kk < 0) kk = 0;
    const float scale = __uint_as_float((u32)(127 - kk) << 23);
    const float c1s = c1 * scale;
    const float c2s = c1 * c1 * scale;

    const int*   arow = adj  + ((size_t)(b * Nn + i0 + iL)) * Nn + jh;
    const float* Ejb  = g_Ej + (size_t)b * Nn + jh;
    const __half* whtb = g_WhT + (size_t)b * FOUT * Nn;

    float acc[2][4][4];
    #pragma unroll
    for (int mt = 0; mt < 2; mt++)
        #pragma unroll
        for (int nt = 0; nt < 4; nt++)
            #pragma unroll
            for (int e = 0; e < 4; e++) acc[mt][nt][e] = 0.f;

    int4   sav[4];
    float4 sev[4];
    float  rs = 0.f;

    #define ISSUE_G(c_) do {                                              \
        const int _j0 = (c_) * CH;                                        \
        _Pragma("unroll")                                                 \
        for (int q = 0; q < 4; q++) {                                     \
            sav[q] = *(const int4*)&arow[_j0 + q * 4];                    \
            sev[q] = *(const float4*)&Ejb[_j0 + q * 4];                   \
        }                                                                  \
    } while (0)

    #define ISSUE_W(c_, buf_) do {                                        \
        const int _j0 = (c_) * CH;                                        \
        const u32 _wb = sb + SM_WS + (buf_) * 16384;                      \
        _Pragma("unroll")                                                 \
        for (int q = 0; q < 4; q++) {                                     \
            int flat = t + 256 * q;                                       \
            int row  = flat >> 3;                                         \
            int jc   = flat & 7;                                          \
            u32 sidx = (u32)(row * 128 + (((u32)(jc ^ (row & 7))) << 4)); \
            CP_ASYNC16(_wb + sidx,                                        \
                       &whtb[(size_t)row * Nn + _j0 + jc * 8]);           \
        }                                                                  \
        CP_COMMIT();                                                       \
    } while (0)

    #define FINISH(buf_) do {                                              \
        const int*   _a = (const int*)sav;                                 \
        const float* _e = (const float*)sev;                               \
        _Pragma("unroll")                                                   \
        for (int q = 0; q < 2; q++) {                                       \
            uint4 pv; u32* pw = (u32*)&pv;                                  \
            _Pragma("unroll")                                               \
            for (int u = 0; u < 4; u++) {                                   \
                int i2 = q * 8 + u * 2;                                     \
                float E0 = _e[i2], E1 = _e[i2 + 1];                         \
                float m0 = (E0 >= thrE) ? c1s : c2s * E0;                   \
                float m1 = (E1 >= thrE) ? c1s : c2s * E1;                   \
                float p0 = (_a[i2]     > 0) ? m0 * E0 : 0.f;                \
                float p1 = (_a[i2 + 1] > 0) ? m1 * E1 : 0.f;                \
                pw[u] = pkh2(p0, p1);                                       \
                rs += p0 + p1;                                              \
            }                                                                \
            *(uint4*)(dsm + SM_PS + (buf_) * 8192 + pst[q]) = pv;           \
        }                                                                    \
    } while (0)

    ISSUE_W(0, 0);
    ISSUE_G(0);
    FINISH(0);
    CP_WAIT0();
    __syncthreads();

    for (int c = 0; c < NCH; c++) {
        const int s = c & 1;
        if (c < NCH - 1) { ISSUE_G(c + 1); ISSUE_W(c + 1, s ^ 1); }

        {
            const u32 pb = sb + SM_PS + s * 8192;
            const u32 wb = sb + SM_WS + s * 16384;
            #pragma unroll
            for (int kb = 0; kb < 2; kb++) {
                u32 bfr[4][4];
                #pragma unroll
                for (int nt = 0; nt < 4; nt++)
                    ldmx4(bfr[nt], wb + b_off[nt][kb]);
                #pragma unroll
                for (int h = 0; h < 2; h++) {
                    u32 afr[2][4];
                    ldmx4(afr[0], pb + a_off[0][kb * 2 + h]);
                    ldmx4(afr[1], pb + a_off[1][kb * 2 + h]);
                    #pragma unroll
                    for (int nt = 0; nt < 4; nt++) {
                        mma16816(acc[0][nt], afr[0], &bfr[nt][h * 2]);
                        mma16816(acc[1][nt], afr[1], &bfr[nt][h * 2]);
                    }
                }
            }
        }

        if (c < NCH - 1) FINISH(s ^ 1);
        CP_WAIT0();
        __syncthreads();
    }

    rs += __shfl_xor_sync(0xffffffffu, rs, 1);
    rs += __shfl_xor_sync(0xffffffffu, rs, 2);
    if ((t & 3) == 0) rows[iL] = rs;
    __syncthreads();

    #pragma unroll
    for (int mt = 0; mt < 2; mt++)
        #pragma unroll
        for (int h = 0; h < 2; h++) {
            const int row = wr * 32 + mt * 16 + g + h * 8;
            const float inv = 1.0f / rows[row];
            float* orow = out + ((size_t)(b * Nn + i0 + row)) * FOUT + wc * 32 + cl * 2;
            #pragma unroll
            for (int nt = 0; nt < 4; nt++) {
                float h0 = acc[mt][nt][h * 2 + 0] * inv;
                float h1 = acc[mt][nt][h * 2 + 1] * inv;
                h0 = (h0 > 0.f) ? h0 : expm1f(h0);
                h1 = (h1 > 0.f) ? h1 : expm1f(h1);
                float2 o = make_float2(h0, h1);
                *(float2*)&orow[nt * 8] = o;
            }
        }
}

// ============================================================
extern "C" void kernel_launch(void* const* d_in, const int* in_sizes, int n_in,
                              void* d_out, int out_size)
{
    const float* x   = (const float*)d_in[0];   // [8,2048,256] f32
    const int*   adj = (const int*)  d_in[1];   // [8,2048,2048] i32
    const float* W   = (const float*)d_in[2];   // [256,128] f32
    const float* a   = (const float*)d_in[3];   // [256,1] f32
    float*       out = (float*)d_out;           // [8,2048,128] f32

    gat_prep<<<8, 256>>>(W, a);

    cudaFuncSetAttribute(gat_gemm_wh, cudaFuncAttributeMaxDynamicSharedMemorySize, K1_TOT);
    cudaFuncSetAttribute(gat_attn,    cudaFuncAttributeMaxDynamicSharedMemorySize, SM_TOT);

    dim3 g1(Nn / 64, Bb);
    gat_gemm_wh<<<g1, 256, K1_TOT>>>(x);

    dim3 g2(Nn / 64, Bb);
    gat_attn<<<g2, 256, SM_TOT>>>(adj, out);
}

// round 16
// speedup vs baseline: 1.6454x; 1.0004x over previous
#include <cuda_runtime.h>
#include <cuda_fp16.h>
#include <math.h>
#include <stdint.h>

#define Bb   8
#define Nn   2048
#define FIN  256
#define FOUT 128
#define CH   64          // attn j-chunk (128-byte fp16 rows)
#define NCH  (Nn / CH)   // 32

typedef unsigned long long u64;
typedef unsigned int u32;

// Scratch (device globals: allocation-free rule)
__device__ __half g_WhT[Bb * FOUT * Nn];   // [b][f][j], fp16
__device__ __half g_Wt16[FOUT * FIN];      // [f][k], fp16 W^T
__device__ float  g_va1[FIN];              // W @ a1
__device__ float  g_va2[FIN];              // W @ a2
__device__ float  g_Ei[Bb * Nn];           // exp(f1) per i-node
__device__ float  g_Ej[Bb * Nn];           // exp(f2) per j-node
__device__ int    g_maxE2i[Bb];            // per-batch max of g_Ej (float bits)

// ---------------- helpers ----------------
__forceinline__ __device__ u32 pkh2(float lo, float hi) {   // lo -> low half
    u32 r; asm("cvt.rn.f16x2.f32 %0,%1,%2;" : "=r"(r) : "f"(hi), "f"(lo)); return r;
}
__forceinline__ __device__ u32 smem_u32(const void* p) {
    u32 a;
    asm("{ .reg .u64 t; cvta.to.shared.u64 t,%1; cvt.u32.u64 %0,t; }" : "=r"(a) : "l"(p));
    return a;
}
__forceinline__ __device__ void mma16816(float* d, const u32* a, const u32* b) {
    asm volatile(
        "mma.sync.aligned.m16n8k16.row.col.f32.f16.f16.f32 "
        "{%0,%1,%2,%3},{%4,%5,%6,%7},{%8,%9},{%0,%1,%2,%3};"
        : "+f"(d[0]), "+f"(d[1]), "+f"(d[2]), "+f"(d[3])
        : "r"(a[0]), "r"(a[1]), "r"(a[2]), "r"(a[3]), "r"(b[0]), "r"(b[1]));
}
__forceinline__ __device__ void ldmx4(u32* d, u32 addr) {
    asm volatile("ldmatrix.sync.aligned.m8n8.x4.shared.b16 {%0,%1,%2,%3},[%4];"
        : "=r"(d[0]), "=r"(d[1]), "=r"(d[2]), "=r"(d[3]) : "r"(addr));
}
#define CP_ASYNC16(sdst, gsrc) \
    asm volatile("cp.async.cg.shared.global [%0], [%1], 16;" :: "r"(sdst), "l"(gsrc))
#define CP_COMMIT()  asm volatile("cp.async.commit_group;" ::: "memory")
#define CP_WAIT0()   asm volatile("cp.async.wait_group 0;" ::: "memory")

// ============================================================
// Kernel 0: prep — coalesced W transpose + va1/va2.
// Grid 32: CTA owns 8 k-rows. One float4 LDG per thread, per-warp
// va reduction, fp16 transpose store. Pad 132: float4-aligned rows.
// ============================================================
__global__ __launch_bounds__(256) void gat_prep(
    const float* __restrict__ W, const float* __restrict__ a)
{
    __shared__ __align__(16) float ws[8][132];   // 528B rows: 16B-aligned
    __shared__ float as[2 * FOUT];
    const int t  = threadIdx.x;
    const int k0 = blockIdx.x * 8;

    as[t] = a[t];
    {
        int flat = t * 4;                 // 0..1023
        int kr   = flat >> 7;             // 0..7
        int f    = flat & 127;
        *(float4*)&ws[kr][f] = *(const float4*)&W[(size_t)(k0 + kr) * FOUT + f];
    }
    __syncthreads();

    // va1/va2: one warp per k-row (kr = t>>5), 4 f's per lane
    {
        const int kr = t >> 5;
        const int f0 = (t & 31) * 4;
        float s1 = 0.f, s2 = 0.f;
        #pragma unroll
        for (int u = 0; u < 4; u++) {
            float w = ws[kr][f0 + u];
            s1 += w * as[f0 + u];
            s2 += w * as[FOUT + f0 + u];
        }
        #pragma unroll
        for (int o = 16; o > 0; o >>= 1) {
            s1 += __shfl_xor_sync(0xffffffffu, s1, o);
            s2 += __shfl_xor_sync(0xffffffffu, s2, o);
        }
        if ((t & 31) == 0) { g_va1[k0 + kr] = s1; g_va2[k0 + kr] = s2; }
    }

    // Wt16 write: thread -> f = t>>1, 4 k's at kh (8 B store)
    {
        const int f  = t >> 1;
        const int kh = (t & 1) * 4;
        uint2 hb;
        hb.x = pkh2(ws[kh + 0][f], ws[kh + 1][f]);
        hb.y = pkh2(ws[kh + 2][f], ws[kh + 3][f]);
        *(uint2*)(g_Wt16 + (size_t)f * FIN + k0 + kh) = hb;
    }
}

// ============================================================
// Kernel 1: fused Wh = x@W (fp16 MMA) + f1/f2 (fp32) + exp + maxE2.
// (unchanged from R14-passing version)
// ============================================================
#define K1_A   0            // 2 x 64 rows x 128 B  = 16384
#define K1_B   16384        // 2 x 128 rows x 128 B = 32768
#define K1_VA  49152        // 2 x 256 floats       = 2048
#define K1_TOT 51200

__global__ __launch_bounds__(256, 2) void gat_gemm_wh(const float* __restrict__ x)
{
    extern __shared__ __align__(16) char dsm[];
    const u32 sb = smem_u32(dsm);
    float* va1s = (float*)(dsm + K1_VA);
    float* va2s = (float*)(dsm + K1_VA + 1024);

    const int t    = threadIdx.x;
    const int lane = t & 31;
    const int wid  = t >> 5;
    const int wr   = wid & 1;
    const int wc   = wid >> 1;
    const int g    = lane >> 2;
    const int cl   = lane & 3;
    const int sel  = lane >> 3, rin = lane & 7;
    const int b    = blockIdx.y;
    const int i0   = blockIdx.x * 64;

    va1s[t] = g_va1[t];
    va2s[t] = g_va2[t];

    u32 a_off[2][4], b_off[4][2];
    #pragma unroll
    for (int mt = 0; mt < 2; mt++)
        #pragma unroll
        for (int ks = 0; ks < 4; ks++) {
            int r = wr * 32 + mt * 16 + ((sel & 1) << 3) + rin;
            int c = ks * 2 + (sel >> 1);
            a_off[mt][ks] = (u32)(r * 128 + ((u32)(c ^ (r & 7)) << 4));
        }
    #pragma unroll
    for (int nt = 0; nt < 4; nt++)
        #pragma unroll
        for (int kb = 0; kb < 2; kb++) {
            int rr = wc * 32 + nt * 8 + rin;
            int c  = kb * 4 + sel;
            b_off[nt][kb] = (u32)(rr * 128 + ((u32)(c ^ (rr & 7)) << 4));
        }

    const int row  = t >> 2;
    const int kseg = (t & 3) * 16;
    const float* xb = x + ((size_t)b * Nn + i0 + row) * FIN + kseg;

    float acc[2][4][4];
    #pragma unroll
    for (int mt = 0; mt < 2; mt++)
        #pragma unroll
        for (int nt = 0; nt < 4; nt++)
            #pragma unroll
            for (int e = 0; e < 4; e++) acc[mt][nt][e] = 0.f;

    float4 xr[4];
    float  f1p = 0.f, f2p = 0.f;

    #define LDX(c_) do {                                                   \
        const float* _p = xb + (c_) * 64;                                  \
        xr[0] = *(const float4*)(_p);                                      \
        xr[1] = *(const float4*)(_p + 4);                                  \
        xr[2] = *(const float4*)(_p + 8);                                  \
        xr[3] = *(const float4*)(_p + 12);                                 \
    } while (0)

    #define BUILD_A(c_, buf_) do {                                         \
        const int _kb = (c_) * 64 + kseg;                                  \
        _Pragma("unroll")                                                  \
        for (int q = 0; q < 4; q++) {                                      \
            float4 v1 = *(const float4*)&va1s[_kb + q * 4];                \
            float4 v2 = *(const float4*)&va2s[_kb + q * 4];                \
            f1p += xr[q].x*v1.x + xr[q].y*v1.y + xr[q].z*v1.z + xr[q].w*v1.w; \
            f2p += xr[q].x*v2.x + xr[q].y*v2.y + xr[q].z*v2.z + xr[q].w*v2.w; \
        }                                                                   \
        uint4 h0, h1;                                                       \
        h0.x = pkh2(xr[0].x, xr[0].y); h0.y = pkh2(xr[0].z, xr[0].w);      \
        h0.z = pkh2(xr[1].x, xr[1].y); h0.w = pkh2(xr[1].z, xr[1].w);      \
        h1.x = pkh2(xr[2].x, xr[2].y); h1.y = pkh2(xr[2].z, xr[2].w);      \
        h1.z = pkh2(xr[3].x, xr[3].y); h1.w = pkh2(xr[3].z, xr[3].w);      \
        u32 jc = (u32)((t & 3) * 2);                                        \
        *(uint4*)(dsm + K1_A + (buf_) * 8192 + row * 128                    \
                  + ((jc ^ (u32)(row & 7)) << 4)) = h0;                     \
        *(uint4*)(dsm + K1_A + (buf_) * 8192 + row * 128                    \
                  + (((jc + 1) ^ (u32)(row & 7)) << 4)) = h1;               \
    } while (0)

    #define ISSUE_B(c_, buf_) do {                                         \
        const int _k0 = (c_) * 64;                                         \
        const u32 _bb = sb + K1_B + (buf_) * 16384;                        \
        _Pragma("unroll")                                                  \
        for (int q = 0; q < 4; q++) {                                      \
            int flat = t + 256 * q;                                        \
            int frow = flat >> 3;                                          \
            int jc2  = flat & 7;                                           \
            u32 sidx = (u32)(frow * 128 + (((u32)(jc2 ^ (frow & 7))) << 4)); \
            CP_ASYNC16(_bb + sidx,                                         \
                       g_Wt16 + (size_t)frow * FIN + _k0 + jc2 * 8);       \
        }                                                                   \
        CP_COMMIT();                                                        \
    } while (0)

    LDX(0);
    ISSUE_B(0, 0);
    __syncthreads();                    // va1s/va2s visible
    BUILD_A(0, 0);
    CP_WAIT0();
    __syncthreads();

    for (int c = 0; c < 4; c++) {
        const int s = c & 1;
        if (c < 3) { LDX(c + 1); ISSUE_B(c + 1, s ^ 1); }

        const u32 ab = sb + K1_A + s * 8192;
        const u32 bb = sb + K1_B + s * 16384;
        #pragma unroll
        for (int kb = 0; kb < 2; kb++) {
            u32 bfr[4][4];
            #pragma unroll
            for (int nt = 0; nt < 4; nt++)
                ldmx4(bfr[nt], bb + b_off[nt][kb]);
            #pragma unroll
            for (int h = 0; h < 2; h++) {
                u32 afr[2][4];
                ldmx4(afr[0], ab + a_off[0][kb * 2 + h]);
                ldmx4(afr[1], ab + a_off[1][kb * 2 + h]);
                #pragma unroll
                for (int nt = 0; nt < 4; nt++) {
                    mma16816(acc[0][nt], afr[0], &bfr[nt][h * 2]);
                    mma16816(acc[1][nt], afr[1], &bfr[nt][h * 2]);
                }
            }
        }

        if (c < 3) BUILD_A(c + 1, s ^ 1);
        CP_WAIT0();
        __syncthreads();
    }

    f1p += __shfl_xor_sync(0xffffffffu, f1p, 1);
    f1p += __shfl_xor_sync(0xffffffffu, f1p, 2);
    f2p += __shfl_xor_sync(0xffffffffu, f2p, 1);
    f2p += __shfl_xor_sync(0xffffffffu, f2p, 2);
    float E2 = 0.f;
    if ((t & 3) == 0) {
        size_t R = (size_t)b * Nn + i0 + row;
        float E1 = __expf(f1p);
        E2 = __expf(f2p);
        g_Ei[R] = E1;
        g_Ej[R] = E2;
    }
    float wm = E2;
    #pragma unroll
    for (int o = 16; o > 0; o >>= 1)
        wm = fmaxf(wm, __shfl_xor_sync(0xffffffffu, wm, o));
    if (lane == 0) atomicMax(&g_maxE2i[b], __float_as_int(wm));

    __half* tr = (__half*)dsm;
    #pragma unroll
    for (int mt = 0; mt < 2; mt++)
        #pragma unroll
        for (int nt = 0; nt < 4; nt++)
            #pragma unroll
            for (int h = 0; h < 2; h++)
                #pragma unroll
                for (int e = 0; e < 2; e++) {
                    int f = wc * 32 + nt * 8 + cl * 2 + e;
                    int j = wr * 32 + mt * 16 + g + 8 * h;
                    tr[(size_t)f * 72 + j] = __float2half(acc[mt][nt][h * 2 + e]);
                }
    __syncthreads();

    {
        const int f   = t >> 1;
        const int seg = (t & 1) * 32;
        const __half* trow = tr + (size_t)f * 72 + seg;
        __half* dst = g_WhT + ((size_t)(b * FOUT + f)) * Nn + i0 + seg;
        #pragma unroll
        for (int m = 0; m < 4; m++)
            *(uint4*)(dst + m * 8) = *(const uint4*)(trow + m * 8);
    }
}

// ============================================================
// Kernel 2: fused attention (unchanged from R14-passing version).
// ============================================================
#define SM_PS   0                        // 2 * 64*128B  = 16384
#define SM_WS   16384                    // 2 * 128*128B = 32768
#define SM_RS   49152                    // 64 floats
#define SM_TOT  49408

__global__ __launch_bounds__(256, 2) void gat_attn(
    const int* __restrict__ adj, float* __restrict__ out)
{
    extern __shared__ __align__(16) char dsm[];
    float* rows = (float*)(dsm + SM_RS);
    const u32 sb = smem_u32(dsm);

    const int t    = threadIdx.x;
    const int lane = t & 31;
    const int wid  = t >> 5;
    const int wr   = wid & 1;
    const int wc   = wid >> 1;
    const int g    = lane >> 2;
    const int cl   = lane & 3;
    const int b    = blockIdx.y;
    const int i0   = blockIdx.x * 64;

    const int sel = lane >> 3, rin = lane & 7;
    u32 a_off[2][4], b_off[4][2];
    #pragma unroll
    for (int mt = 0; mt < 2; mt++)
        #pragma unroll
        for (int ks = 0; ks < 4; ks++) {
            int r = wr * 32 + mt * 16 + ((sel & 1) << 3) + rin;
            int c = ks * 2 + (sel >> 1);
            a_off[mt][ks] = (u32)(r * 128 + ((u32)(c ^ (r & 7)) << 4));
        }
    #pragma unroll
    for (int nt = 0; nt < 4; nt++)
        #pragma unroll
        for (int kb = 0; kb < 2; kb++) {
            int rr = wc * 32 + nt * 8 + rin;
            int c  = kb * 4 + sel;
            b_off[nt][kb] = (u32)(rr * 128 + ((u32)(c ^ (rr & 7)) << 4));
        }

    const int iL = t >> 2;
    const int jq = t & 3;
    const int jh = jq * 16;
    u32 pst[2];
    #pragma unroll
    for (int q = 0; q < 2; q++)
        pst[q] = (u32)(iL * 128 + (((u32)((jq * 2 + q) ^ (iL & 7))) << 4));

    const float c1  = g_Ei[(size_t)b * Nn + i0 + iL];
    const float mE2 = __int_as_float(g_maxE2i[b]);
    const float thrE = 1.0f / c1;
    float pm = c1 * mE2;
    pm = (pm >= 1.f) ? pm : pm * pm;
    int ex = (int)((__float_as_uint(pm) >> 23) & 255u) - 127;
    int kk = ex - 11; if (kk < 0) kk = 0;
    const float scale = __uint_as_float((u32)(127 - kk) << 23);
    const float c1s = c1 * scale;
    const float c2s = c1 * c1 * scale;

    const int*   arow = adj  + ((size_t)(b * Nn + i0 + iL)) * Nn + jh;
    const float* Ejb  = g_Ej + (size_t)b * Nn + jh;
    const __half* whtb = g_WhT + (size_t)b * FOUT * Nn;

    float acc[2][4][4];
    #pragma unroll
    for (int mt = 0; mt < 2; mt++)
        #pragma unroll
        for (int nt = 0; nt < 4; nt++)
            #pragma unroll
            for (int e = 0; e < 4; e++) acc[mt][nt][e] = 0.f;

    int4   sav[4];
    float4 sev[4];
    float  rs = 0.f;

    #define ISSUE_G(c_) do {                                              \
        const int _j0 = (c_) * CH;                                        \
        _Pragma("unroll")                                                 \
        for (int q = 0; q < 4; q++) {                                     \
            sav[q] = *(const int4*)&arow[_j0 + q * 4];                    \
            sev[q] = *(const float4*)&Ejb[_j0 + q * 4];                   \
        }                                                                  \
    } while (0)

    #define ISSUE_W(c_, buf_) do {                                        \
        const int _j0 = (c_) * CH;                                        \
        const u32 _wb = sb + SM_WS + (buf_) * 16384;                      \
        _Pragma("unroll")                                                 \
        for (int q = 0; q < 4; q++) {                                     \
            int flat = t + 256 * q;                                       \
            int row  = flat >> 3;                                         \
            int jc   = flat & 7;                                          \
            u32 sidx = (u32)(row * 128 + (((u32)(jc ^ (row & 7))) << 4)); \
            CP_ASYNC16(_wb + sidx,                                        \
                       &whtb[(size_t)row * Nn + _j0 + jc * 8]);           \
        }                                                                  \
        CP_COMMIT();                                                       \
    } while (0)

    #define FINISH(buf_) do {                                              \
        const int*   _a = (const int*)sav;                                 \
        const float* _e = (const float*)sev;                               \
        _Pragma("unroll")                                                   \
        for (int q = 0; q < 2; q++) {                                       \
            uint4 pv; u32* pw = (u32*)&pv;                                  \
            _Pragma("unroll")                                               \
            for (int u = 0; u < 4; u++) {                                   \
                int i2 = q * 8 + u * 2;                                     \
                float E0 = _e[i2], E1 = _e[i2 + 1];                         \
                float m0 = (E0 >= thrE) ? c1s : c2s * E0;                   \
                float m1 = (E1 >= thrE) ? c1s : c2s * E1;                   \
                float p0 = (_a[i2]     > 0) ? m0 * E0 : 0.f;                \
                float p1 = (_a[i2 + 1] > 0) ? m1 * E1 : 0.f;                \
                pw[u] = pkh2(p0, p1);                                       \
                rs += p0 + p1;                                              \
            }                                                                \
            *(uint4*)(dsm + SM_PS + (buf_) * 8192 + pst[q]) = pv;           \
        }                                                                    \
    } while (0)

    ISSUE_W(0, 0);
    ISSUE_G(0);
    FINISH(0);
    CP_WAIT0();
    __syncthreads();

    for (int c = 0; c < NCH; c++) {
        const int s = c & 1;
        if (c < NCH - 1) { ISSUE_G(c + 1); ISSUE_W(c + 1, s ^ 1); }

        {
            const u32 pb = sb + SM_PS + s * 8192;
            const u32 wb = sb + SM_WS + s * 16384;
            #pragma unroll
            for (int kb = 0; kb < 2; kb++) {
                u32 bfr[4][4];
                #pragma unroll
                for (int nt = 0; nt < 4; nt++)
                    ldmx4(bfr[nt], wb + b_off[nt][kb]);
                #pragma unroll
                for (int h = 0; h < 2; h++) {
                    u32 afr[2][4];
                    ldmx4(afr[0], pb + a_off[0][kb * 2 + h]);
                    ldmx4(afr[1], pb + a_off[1][kb * 2 + h]);
                    #pragma unroll
                    for (int nt = 0; nt < 4; nt++) {
                        mma16816(acc[0][nt], afr[0], &bfr[nt][h * 2]);
                        mma16816(acc[1][nt], afr[1], &bfr[nt][h * 2]);
                    }
                }
            }
        }

        if (c < NCH - 1) FINISH(s ^ 1);
        CP_WAIT0();
        __syncthreads();
    }

    rs += __shfl_xor_sync(0xffffffffu, rs, 1);
    rs += __shfl_xor_sync(0xffffffffu, rs, 2);
    if ((t & 3) == 0) rows[iL] = rs;
    __syncthreads();

    #pragma unroll
    for (int mt = 0; mt < 2; mt++)
        #pragma unroll
        for (int h = 0; h < 2; h++) {
            const int row = wr * 32 + mt * 16 + g + h * 8;
            const float inv = 1.0f / rows[row];
            float* orow = out + ((size_t)(b * Nn + i0 + row)) * FOUT + wc * 32 + cl * 2;
            #pragma unroll
            for (int nt = 0; nt < 4; nt++) {
                float h0 = acc[mt][nt][h * 2 + 0] * inv;
                float h1 = acc[mt][nt][h * 2 + 1] * inv;
                h0 = (h0 > 0.f) ? h0 : expm1f(h0);
                h1 = (h1 > 0.f) ? h1 : expm1f(h1);
                float2 o = make_float2(h0, h1);
                *(float2*)&orow[nt * 8] = o;
            }
        }
}

// ============================================================
extern "C" void kernel_launch(void* const* d_in, const int* in_sizes, int n_in,
                              void* d_out, int out_size)
{
    const float* x   = (const float*)d_in[0];   // [8,2048,256] f32
    const int*   adj = (const int*)  d_in[1];   // [8,2048,2048] i32
    const float* W   = (const float*)d_in[2];   // [256,128] f32
    const float* a   = (const float*)d_in[3];   // [256,1] f32
    float*       out = (float*)d_out;           // [8,2048,128] f32

    gat_prep<<<32, 256>>>(W, a);

    cudaFuncSetAttribute(gat_gemm_wh, cudaFuncAttributeMaxDynamicSharedMemorySize, K1_TOT);
    cudaFuncSetAttribute(gat_attn,    cudaFuncAttributeMaxDynamicSharedMemorySize, SM_TOT);

    dim3 g1(Nn / 64, Bb);
    gat_gemm_wh<<<g1, 256, K1_TOT>>>(x);

    dim3 g2(Nn / 64, Bb);
    gat_attn<<<g2, 256, SM_TOT>>>(adj, out);
}